// round 15
// baseline (speedup 1.0000x reference)
#include <cuda_runtime.h>
#include <math.h>
#include <stdint.h>

#define BB 4
#define TT 1024
#define EE 512
#define HH 8
#define DHH 64
#define KVL 2304
#define MEML 1024
#define CMEML 256
#define SCL 0.125f
#define PEROWS 3456

#define OFF_LOGITS  0LL
#define OFF_NEWMEM  2097152LL
#define OFF_NEWCMEM 4194304LL
#define OFF_AUX     4718592LL
#define OFF_W       4718593LL   /* ODD -> weights region only 4B-aligned: scalar I/O only */

#define S_Q     0LL
#define S_KVIN  2097152LL
#define S_KV    6815744LL
#define S_CM    16252928LL
#define S_CKV   16777216LL
#define S_CONVA 17825792LL
#define S_O     19922944LL
#define S_AUXP  22020096LL
#define S_M     22020608LL
#define S_L     22053376LL
#define S_PE    22086144LL
#define S_TOTAL (S_PE + (long long)HH*PEROWS*64)

__device__ float g_scratch[S_TOTAL];

__device__ __forceinline__ float tf32r(float x){
    unsigned u;
    asm("cvt.rna.tf32.f32 %0, %1;" : "=r"(u) : "f"(x));
    return __uint_as_float(u);
}

__device__ __forceinline__ void mma_tf32(float d[4], const unsigned a[4], const unsigned b[2]){
    asm("mma.sync.aligned.m16n8k8.row.col.f32.tf32.tf32.f32 "
        "{%0,%1,%2,%3},{%4,%5,%6,%7},{%8,%9},{%0,%1,%2,%3};"
        : "+f"(d[0]),"+f"(d[1]),"+f"(d[2]),"+f"(d[3])
        : "r"(a[0]),"r"(a[1]),"r"(a[2]),"r"(a[3]), "r"(b[0]),"r"(b[1]));
}

__global__ void k_concat(const float* __restrict__ x, const float* __restrict__ mem,
                         const float* __restrict__ cmem, float* __restrict__ kvin){
    long long i = (long long)blockIdx.x*blockDim.x + threadIdx.x;
    const long long n4 = (long long)BB*KVL*EE/4;
    if(i >= n4) return;
    long long idx = i*4;
    int b = (int)(idx / ((long long)KVL*EE));
    int rem = (int)(idx % ((long long)KVL*EE));
    int j = rem / EE, e = rem % EE;
    const float* src;
    if(j < CMEML)            src = cmem + ((long long)b*CMEML + j)*EE + e;
    else if(j < CMEML+MEML)  src = mem  + ((long long)b*MEML + (j-CMEML))*EE + e;
    else                     src = x    + ((long long)b*TT   + (j-CMEML-MEML))*EE + e;
    ((float4*)kvin)[i] = *(const float4*)src;
}

__global__ void k_convA(const float* __restrict__ mem, float* __restrict__ convA){
    int i = blockIdx.x*blockDim.x + threadIdx.x;
    if(i >= BB*CMEML*EE*4) return;
    int b = i >> 19;
    int rem = i & ((1<<19)-1);
    int r = rem >> 11;
    int t2 = rem & 2047;
    int e = t2 >> 2, kk = t2 & 3;
    convA[i] = mem[((long long)b*MEML + r*4 + kk)*EE + e];
}

__global__ void k_pe(const float* __restrict__ pe, float* __restrict__ spe){
    int i = blockIdx.x*blockDim.x + threadIdx.x;
    if(i >= HH*PEROWS*64/4) return;
    int idx = i*4;
    int h = idx / (PEROWS*64);
    int rem = idx % (PEROWS*64);
    int r = rem >> 6, c = rem & 63;
    float4 v = make_float4(0.f,0.f,0.f,0.f);
    if(r < KVL){
        float4 s = *(const float4*)(pe + ((long long)h*KVL + r)*64 + c);
        v.x = tf32r(s.x); v.y = tf32r(s.y); v.z = tf32r(s.z); v.w = tf32r(s.w);
    }
    ((float4*)spe)[i] = v;
}

// ============ tf32 mma GEMM. RND=1 -> store tf32-rounded ============
template<int BT, int RND>
__global__ void __launch_bounds__(256) k_gemm_mma(const float* __restrict__ A,
                                                  const float* __restrict__ Bm,
                                                  const float* __restrict__ bias,
                                                  float* __restrict__ C,
                                                  int M, int N, int K){
    __shared__ float As[128*20];
    __shared__ float Bs[16*68];
    const int tid = threadIdx.x;
    const int w = tid >> 5, lane = tid & 31;
    const int g = lane >> 2, q = lane & 3;
    const int wm = w & 3, wn = w >> 2;
    const int m0 = blockIdx.y * 128;
    const int n0 = blockIdx.x * 64;

    float acc[2][4][4];
    #pragma unroll
    for(int mt=0;mt<2;mt++)
        #pragma unroll
        for(int nt=0;nt<4;nt++)
            #pragma unroll
            for(int e=0;e<4;e++) acc[mt][nt][e] = 0.f;

    const unsigned* Asu = (const unsigned*)As;
    const unsigned* Bsu = (const unsigned*)Bs;

    for(int k0=0; k0<K; k0+=16){
        #pragma unroll
        for(int li=0; li<2; li++){
            int idx = tid + li*256;
            int row = idx >> 2, c4 = (idx & 3)*4;
            float4 v = *(const float4*)(A + (long long)(m0+row)*K + k0 + c4);
            As[row*20 + c4 + 0] = tf32r(v.x);
            As[row*20 + c4 + 1] = tf32r(v.y);
            As[row*20 + c4 + 2] = tf32r(v.z);
            As[row*20 + c4 + 3] = tf32r(v.w);
        }
        if(BT){
            #pragma unroll
            for(int li=0; li<4; li++){
                int idx = tid + li*256;
                int n = idx & 63, kk = idx >> 6;
                Bs[kk*68 + n] = tf32r(Bm[(long long)(n0+n)*K + k0 + kk]);
            }
        } else {
            int row = tid >> 4, c4 = (tid & 15)*4;
            float4 v = *(const float4*)(Bm + (long long)(k0+row)*N + n0 + c4);
            Bs[row*68 + c4 + 0] = tf32r(v.x);
            Bs[row*68 + c4 + 1] = tf32r(v.y);
            Bs[row*68 + c4 + 2] = tf32r(v.z);
            Bs[row*68 + c4 + 3] = tf32r(v.w);
        }
        __syncthreads();
        #pragma unroll
        for(int k8=0; k8<2; k8++){
            int kr = k8*8;
            #pragma unroll
            for(int mt=0; mt<2; mt++){
                unsigned a[4];
                int mb = wm*32 + mt*16;
                a[0] = Asu[(mb+g)*20   + kr+q];
                a[1] = Asu[(mb+g+8)*20 + kr+q];
                a[2] = Asu[(mb+g)*20   + kr+q+4];
                a[3] = Asu[(mb+g+8)*20 + kr+q+4];
                #pragma unroll
                for(int nt=0; nt<4; nt++){
                    unsigned b[2];
                    int nb = wn*32 + nt*8;
                    b[0] = Bsu[(kr+q)*68   + nb+g];
                    b[1] = Bsu[(kr+q+4)*68 + nb+g];
                    mma_tf32(acc[mt][nt], a, b);
                }
            }
        }
        __syncthreads();
    }
    #pragma unroll
    for(int mt=0; mt<2; mt++){
        int r1 = m0 + wm*32 + mt*16 + g;
        #pragma unroll
        for(int nt=0; nt<4; nt++){
            int col = n0 + wn*32 + nt*8 + 2*q;
            float b0 = bias ? bias[col] : 0.f;
            float b1 = bias ? bias[col+1] : 0.f;
            float v0 = acc[mt][nt][0] + b0, v1 = acc[mt][nt][1] + b1;
            float v2 = acc[mt][nt][2] + b0, v3 = acc[mt][nt][3] + b1;
            if(RND){ v0=tf32r(v0); v1=tf32r(v1); v2=tf32r(v2); v3=tf32r(v3); }
            C[(long long)r1*N + col]       = v0;
            C[(long long)r1*N + col+1]     = v1;
            C[(long long)(r1+8)*N + col]   = v2;
            C[(long long)(r1+8)*N + col+1] = v3;
        }
    }
}

// ===== attention: packed Q/P, u aliased on pe, direct register score dump,
//       batch-offset b0 for pipelined launches; writes m/l =====
__global__ void __launch_bounds__(256,2) k_attn_mma(const float* __restrict__ spe,
                                                    float* __restrict__ wout,
                                                    const float* __restrict__ gq,
                                                    const float* __restrict__ gkv,
                                                    float* __restrict__ go,
                                                    float* __restrict__ gm,
                                                    float* __restrict__ gl,
                                                    int b0){
    extern __shared__ float smx[];
    float* qp    = smx;                 // 4224: packed Q (A-fragments)
    float* k_s   = qp + 4224;           // 4352
    float* v_s   = k_s + 4352;          // 4352 [d][68]
    float* p_s   = v_s + 4352;          // 4352 [64][68]
    float* pu_s  = p_s + 4352;          // 8704: PE [128][68] ALIAS u [64][132] ALIAS packed P
    float* m_row = pu_s + 8704;
    float* l_row = m_row + 64;
    float* corr_row = l_row + 64;

    const int it = blockIdx.x, h = blockIdx.y, b = blockIdx.z + b0;
    const int i0 = it*64;
    const int t = threadIdx.x;
    const int w = t >> 5, lane = t & 31;
    const int g = lane >> 2, q = lane & 3;
    const int mw = w & 3, half = w >> 2;

    const float* kbase  = gkv + ((long long)b*KVL)*1024 + h*64;
    const float* vbase  = kbase + 512;
    const float* pebase = spe + (long long)h*PEROWS*64;
    const long long wbase = (((long long)(b*HH + h))*TT + i0)*KVL;

    #pragma unroll
    for(int li=0; li<4; li++){
        int idx = t + li*256;
        int row = idx >> 4, c4 = (idx & 15)*4;
        float4 v = *(const float4*)(gq + ((long long)(b*TT+i0+row))*EE + h*64 + c4);
        int base = ((row>>4)*8 + (c4>>3))*132 + (row&7)*16 + ((row>>3)&1) + 2*((c4>>2)&1);
        qp[base+0]  = v.x;
        qp[base+4]  = v.y;
        qp[base+8]  = v.z;
        qp[base+12] = v.w;
    }
    if(t < 64){ m_row[t] = -INFINITY; l_row[t] = 0.f; }

    float oacc[4][4];
    #pragma unroll
    for(int nt=0;nt<4;nt++)
        #pragma unroll
        for(int e=0;e<4;e++) oacc[nt][e] = 0.f;

    const unsigned* ksu = (const unsigned*)k_s;
    const unsigned* vsu = (const unsigned*)v_s;
    const unsigned* peu = (const unsigned*)pu_s;

    for(int ch=0; ch<KVL/64; ch++){
        const int j0 = ch*64;
        const int rb = 960 + j0 - i0;
        const bool useU = (rb < KVL);
        __syncthreads();
        #pragma unroll
        for(int li=0; li<4; li++){
            int idx = t + li*256;
            int row = idx >> 4, c4 = (idx & 15)*4;
            *(float4*)(k_s + row*68 + c4) =
                *(const float4*)(kbase + (long long)(j0+row)*1024 + c4);
            float4 vv = *(const float4*)(vbase + (long long)(j0+row)*1024 + c4);
            v_s[(c4+0)*68 + row] = vv.x;
            v_s[(c4+1)*68 + row] = vv.y;
            v_s[(c4+2)*68 + row] = vv.z;
            v_s[(c4+3)*68 + row] = vv.w;
        }
        if(useU){
            #pragma unroll
            for(int li=0; li<8; li++){
                int idx = t + li*256;
                int row = idx >> 4, c4 = (idx & 15)*4;
                *(float4*)(pu_s + row*68 + c4) =
                    *(const float4*)(pebase + (long long)(rb+row)*64 + c4);
            }
        }
        __syncthreads();

        float uacc[8][4], sacc[4][4];
        #pragma unroll
        for(int nt=0;nt<8;nt++){ uacc[nt][0]=0.f; uacc[nt][1]=0.f; uacc[nt][2]=0.f; uacc[nt][3]=0.f; }
        #pragma unroll
        for(int nt=0;nt<4;nt++){ sacc[nt][0]=0.f; sacc[nt][1]=0.f; sacc[nt][2]=0.f; sacc[nt][3]=0.f; }
        #pragma unroll
        for(int ks=0; ks<8; ks++){
            float4 af = *(const float4*)(qp + (mw*8+ks)*132 + lane*4);
            unsigned a[4] = {__float_as_uint(af.x), __float_as_uint(af.y),
                             __float_as_uint(af.z), __float_as_uint(af.w)};
            int k0 = ks*8;
            if(useU){
                #pragma unroll
                for(int nt=0; nt<8; nt++){
                    unsigned bb[2];
                    int nb = half*64 + nt*8;
                    bb[0] = peu[(nb+g)*68 + k0+q];
                    bb[1] = peu[(nb+g)*68 + k0+q+4];
                    mma_tf32(uacc[nt], a, bb);
                }
            }
            #pragma unroll
            for(int nt=0; nt<4; nt++){
                unsigned bb[2];
                int nb = half*32 + nt*8;
                bb[0] = ksu[(nb+g)*68 + k0+q];
                bb[1] = ksu[(nb+g)*68 + k0+q+4];
                mma_tf32(sacc[nt], a, bb);
            }
        }
        if(useU){
            __syncthreads();
            int i1 = mw*16 + g, i2 = i1 + 8;
            #pragma unroll
            for(int nt=0; nt<8; nt++){
                int rho = half*64 + nt*8 + 2*q;
                pu_s[i1*132 + rho]   = uacc[nt][0];
                pu_s[i1*132 + rho+1] = uacc[nt][1];
                pu_s[i2*132 + rho]   = uacc[nt][2];
                pu_s[i2*132 + rho+1] = uacc[nt][3];
            }
            __syncthreads();
        }
        {
            int i1 = mw*16 + g, i2 = i1 + 8;
            #pragma unroll
            for(int nt=0; nt<4; nt++){
                int j_ = half*32 + nt*8 + 2*q;
                float s0,s1,s2,s3;
                if(useU){
                    s0 = SCL*(sacc[nt][0] + pu_s[i1*132 + 63 + j_   - i1]);
                    s1 = SCL*(sacc[nt][1] + pu_s[i1*132 + 63 + j_+1 - i1]);
                    s2 = SCL*(sacc[nt][2] + pu_s[i2*132 + 63 + j_   - i2]);
                    s3 = SCL*(sacc[nt][3] + pu_s[i2*132 + 63 + j_+1 - i2]);
                } else {
                    s0 = SCL*sacc[nt][0];
                    s1 = SCL*sacc[nt][1];
                    s2 = SCL*sacc[nt][2];
                    s3 = SCL*sacc[nt][3];
                }
                p_s[i1*68 + j_]   = s0;
                p_s[i1*68 + j_+1] = s1;
                p_s[i2*68 + j_]   = s2;
                p_s[i2*68 + j_+1] = s3;
                // direct raw-score dump from registers (scalar: wout is 4B-aligned)
                long long wa1 = wbase + (long long)i1*KVL + j0 + j_;
                long long wa2 = wbase + (long long)i2*KVL + j0 + j_;
                wout[wa1]   = s0;
                wout[wa1+1] = s1;
                wout[wa2]   = s2;
                wout[wa2+1] = s3;
            }
        }
        __syncthreads();
        {
            int r = w*8 + (lane>>2);
            int c0 = lane & 3;
            const int R8 = (r>>4)*8;
            const int WB = ((r&7)*4 + c0)*4 + ((r>>3)&1);
            float vals[16];
            float mx = -INFINITY;
            #pragma unroll
            for(int ii=0; ii<16; ii++){
                vals[ii] = p_s[r*68 + c0 + ii*4];
                mx = fmaxf(mx, vals[ii]);
            }
            mx = fmaxf(mx, __shfl_xor_sync(0xffffffffu, mx, 1));
            mx = fmaxf(mx, __shfl_xor_sync(0xffffffffu, mx, 2));
            float mo = m_row[r];
            float mn = fmaxf(mo, mx);
            float corr = __expf(mo - mn);
            float ps = 0.f;
            #pragma unroll
            for(int ii=0; ii<16; ii++){
                float p = tf32r(__expf(vals[ii] - mn));
                pu_s[(R8 + ((c0+4*ii)>>3))*132 + WB + 2*(ii&1)] = p;
                ps += p;
            }
            ps += __shfl_xor_sync(0xffffffffu, ps, 1);
            ps += __shfl_xor_sync(0xffffffffu, ps, 2);
            if((lane&3)==0){
                l_row[r] = l_row[r]*corr + ps;
                m_row[r] = mn;
                corr_row[r] = corr;
            }
        }
        __syncthreads();
        {
            float c1 = corr_row[mw*16+g], c2 = corr_row[mw*16+g+8];
            #pragma unroll
            for(int nt=0; nt<4; nt++){
                oacc[nt][0] *= c1; oacc[nt][1] *= c1;
                oacc[nt][2] *= c2; oacc[nt][3] *= c2;
            }
            #pragma unroll
            for(int ks=0; ks<8; ks++){
                float4 af = *(const float4*)(pu_s + (mw*8+ks)*132 + lane*4);
                unsigned a[4] = {__float_as_uint(af.x), __float_as_uint(af.y),
                                 __float_as_uint(af.z), __float_as_uint(af.w)};
                int k0 = ks*8;
                #pragma unroll
                for(int nt=0; nt<4; nt++){
                    unsigned bb[2];
                    int db = half*32 + nt*8;
                    bb[0] = vsu[(db+g)*68 + k0+q];
                    bb[1] = vsu[(db+g)*68 + k0+q+4];
                    mma_tf32(oacc[nt], a, bb);
                }
            }
        }
    }
    __syncthreads();
    {
        int i1 = mw*16 + g, i2 = i1 + 8;
        float inv1 = 1.f/l_row[i1], inv2 = 1.f/l_row[i2];
        #pragma unroll
        for(int nt=0; nt<4; nt++){
            int d_ = half*32 + nt*8 + 2*q;
            long long o1 = ((long long)(b*TT + i0 + i1))*EE + h*64 + d_;
            long long o2 = ((long long)(b*TT + i0 + i2))*EE + h*64 + d_;
            go[o1]   = oacc[nt][0]*inv1;
            go[o1+1] = oacc[nt][1]*inv1;
            go[o2]   = oacc[nt][2]*inv2;
            go[o2+1] = oacc[nt][3]*inv2;
        }
    }
    if(t < 64){
        long long gmi = ((long long)(b*HH + h))*TT + i0 + t;
        gm[gmi] = m_row[t];
        gl[gmi] = l_row[t];
    }
}

// rescale with row offset (half-grid launches)
__global__ void __launch_bounds__(576) k_rescale(float* __restrict__ w,
                                                 const float* __restrict__ gm,
                                                 const float* __restrict__ gl,
                                                 int roff){
    long long row = blockIdx.x + roff;
    float mm = gm[row];
    float invl = 1.f / gl[row];
    float* wr = w + row*KVL;
    #pragma unroll
    for(int rep=0; rep<4; rep++){
        int j = threadIdx.x + rep*576;
        wr[j] = __expf(wr[j] - mm) * invl;
    }
}

// ===== aux loss: packed Q + packed P =====
__global__ void __launch_bounds__(256,2) k_aux_mma(const float* __restrict__ gq,
                                                   const float* __restrict__ gkv,
                                                   const float* __restrict__ gckv,
                                                   float* __restrict__ auxp){
    extern __shared__ float smx[];
    float* qp    = smx;                 // 4224
    float* k_s   = qp + 4224;           // 4352
    float* v_s   = k_s + 4352;          // 4352
    float* p_s   = v_s + 4352;          // 4352
    float* o1_s  = p_s + 4352;          // 4352
    float* pp    = o1_s + 4352;         // 4224 packed P
    float* m_row = pp + 4224;
    float* l_row = m_row + 64;
    float* corr_row = l_row + 64;
    float* red   = corr_row + 64;       // 256

    const int it = blockIdx.x, h = blockIdx.y, b = blockIdx.z;
    const int i0 = it*64;
    const int t = threadIdx.x;
    const int w = t >> 5, lane = t & 31;
    const int g = lane >> 2, q = lane & 3;
    const int mw = w & 3, half = w >> 2;

    #pragma unroll
    for(int li=0; li<4; li++){
        int idx = t + li*256;
        int row = idx >> 4, c4 = (idx & 15)*4;
        float4 v = *(const float4*)(gq + ((long long)(b*TT+i0+row))*EE + h*64 + c4);
        int base = ((row>>4)*8 + (c4>>3))*132 + (row&7)*16 + ((row>>3)&1) + 2*((c4>>2)&1);
        qp[base+0]  = v.x;
        qp[base+4]  = v.y;
        qp[base+8]  = v.z;
        qp[base+12] = v.w;
    }

    const unsigned* ksu = (const unsigned*)k_s;
    const unsigned* vsu = (const unsigned*)v_s;

    float dsum = 0.f;
    for(int pass=0; pass<2; pass++){
        const int nch = pass ? (CMEML/64) : (MEML/64);
        const float* kb = pass ? (gckv + ((long long)b*CMEML)*1024 + h*64)
                               : (gkv  + ((long long)(b*KVL + CMEML))*1024 + h*64);
        __syncthreads();
        if(t < 64){ m_row[t] = -INFINITY; l_row[t] = 0.f; }
        float oacc[4][4];
        #pragma unroll
        for(int nt=0;nt<4;nt++)
            #pragma unroll
            for(int e=0;e<4;e++) oacc[nt][e] = 0.f;

        for(int ch=0; ch<nch; ch++){
            const int j0 = ch*64;
            __syncthreads();
            #pragma unroll
            for(int li=0; li<4; li++){
                int idx = t + li*256;
                int row = idx >> 4, c4 = (idx & 15)*4;
                *(float4*)(k_s + row*68 + c4) =
                    *(const float4*)(kb + (long long)(j0+row)*1024 + c4);
                float4 vv = *(const float4*)(kb + (long long)(j0+row)*1024 + 512 + c4);
                v_s[(c4+0)*68 + row] = vv.x;
                v_s[(c4+1)*68 + row] = vv.y;
                v_s[(c4+2)*68 + row] = vv.z;
                v_s[(c4+3)*68 + row] = vv.w;
            }
            __syncthreads();
            float sacc[4][4];
            #pragma unroll
            for(int nt=0;nt<4;nt++){ sacc[nt][0]=0.f; sacc[nt][1]=0.f; sacc[nt][2]=0.f; sacc[nt][3]=0.f; }
            #pragma unroll
            for(int ks=0; ks<8; ks++){
                float4 af = *(const float4*)(qp + (mw*8+ks)*132 + lane*4);
                unsigned a[4] = {__float_as_uint(af.x), __float_as_uint(af.y),
                                 __float_as_uint(af.z), __float_as_uint(af.w)};
                int k0 = ks*8;
                #pragma unroll
                for(int nt=0; nt<4; nt++){
                    unsigned bb[2];
                    int nb = half*32 + nt*8;
                    bb[0] = ksu[(nb+g)*68 + k0+q];
                    bb[1] = ksu[(nb+g)*68 + k0+q+4];
                    mma_tf32(sacc[nt], a, bb);
                }
            }
            {
                int i1 = mw*16 + g, i2 = i1 + 8;
                #pragma unroll
                for(int nt=0; nt<4; nt++){
                    int j_ = half*32 + nt*8 + 2*q;
                    p_s[i1*68 + j_]   = SCL*sacc[nt][0];
                    p_s[i1*68 + j_+1] = SCL*sacc[nt][1];
                    p_s[i2*68 + j_]   = SCL*sacc[nt][2];
                    p_s[i2*68 + j_+1] = SCL*sacc[nt][3];
                }
            }
            __syncthreads();
            {
                int r = w*8 + (lane>>2);
                int c0 = lane & 3;
                const int R8 = (r>>4)*8;
                const int WB = ((r&7)*4 + c0)*4 + ((r>>3)&1);
                float vals[16];
                float mx = -INFINITY;
                #pragma unroll
                for(int ii=0; ii<16; ii++){
                    vals[ii] = p_s[r*68 + c0 + ii*4];
                    mx = fmaxf(mx, vals[ii]);
                }
                mx = fmaxf(mx, __shfl_xor_sync(0xffffffffu, mx, 1));
                mx = fmaxf(mx, __shfl_xor_sync(0xffffffffu, mx, 2));
                float mo = m_row[r];
                float mn = fmaxf(mo, mx);
                float corr = __expf(mo - mn);
                float ps = 0.f;
                #pragma unroll
                for(int ii=0; ii<16; ii++){
                    float p = tf32r(__expf(vals[ii] - mn));
                    pp[(R8 + ((c0+4*ii)>>3))*132 + WB + 2*(ii&1)] = p;
                    ps += p;
                }
                ps += __shfl_xor_sync(0xffffffffu, ps, 1);
                ps += __shfl_xor_sync(0xffffffffu, ps, 2);
                if((lane&3)==0){
                    l_row[r] = l_row[r]*corr + ps;
                    m_row[r] = mn;
                    corr_row[r] = corr;
                }
            }
            __syncthreads();
            {
                float c1 = corr_row[mw*16+g], c2 = corr_row[mw*16+g+8];
                #pragma unroll
                for(int nt=0; nt<4; nt++){
                    oacc[nt][0] *= c1; oacc[nt][1] *= c1;
                    oacc[nt][2] *= c2; oacc[nt][3] *= c2;
                }
                #pragma unroll
                for(int ks=0; ks<8; ks++){
                    float4 af = *(const float4*)(pp + (mw*8+ks)*132 + lane*4);
                    unsigned a[4] = {__float_as_uint(af.x), __float_as_uint(af.y),
                                     __float_as_uint(af.z), __float_as_uint(af.w)};
                    int k0 = ks*8;
                    #pragma unroll
                    for(int nt=0; nt<4; nt++){
                        unsigned bb[2];
                        int db = half*32 + nt*8;
                        bb[0] = vsu[(db+g)*68 + k0+q];
                        bb[1] = vsu[(db+g)*68 + k0+q+4];
                        mma_tf32(oacc[nt], a, bb);
                    }
                }
            }
        }
        __syncthreads();
        {
            int i1 = mw*16 + g, i2 = i1 + 8;
            float inv1 = 1.f/l_row[i1], inv2 = 1.f/l_row[i2];
            if(pass == 0){
                #pragma unroll
                for(int nt=0; nt<4; nt++){
                    int d_ = half*32 + nt*8 + 2*q;
                    o1_s[i1*68 + d_]   = oacc[nt][0]*inv1;
                    o1_s[i1*68 + d_+1] = oacc[nt][1]*inv1;
                    o1_s[i2*68 + d_]   = oacc[nt][2]*inv2;
                    o1_s[i2*68 + d_+1] = oacc[nt][3]*inv2;
                }
            } else {
                #pragma unroll
                for(int nt=0; nt<4; nt++){
                    int d_ = half*32 + nt*8 + 2*q;
                    float d0 = o1_s[i1*68 + d_]   - oacc[nt][0]*inv1;
                    float d1 = o1_s[i1*68 + d_+1] - oacc[nt][1]*inv1;
                    float d2 = o1_s[i2*68 + d_]   - oacc[nt][2]*inv2;
                    float d3 = o1_s[i2*68 + d_+1] - oacc[nt][3]*inv2;
                    dsum += d0*d0 + d1*d1 + d2*d2 + d3*d3;
                }
            }
        }
    }
    red[t] = dsum;
    __syncthreads();
    for(int s2=128; s2>0; s2>>=1){
        if(t < s2) red[t] += red[t + s2];
        __syncthreads();
    }
    if(t == 0)
        auxp[(blockIdx.z*8 + blockIdx.y)*16 + blockIdx.x] = red[0];
}

__global__ void k_auxfin(const float* __restrict__ auxp, float* __restrict__ dst){
    __shared__ float red[512];
    int t = threadIdx.x;
    red[t] = auxp[t];
    __syncthreads();
    for(int s2=256; s2>0; s2>>=1){
        if(t < s2) red[t] += red[t + s2];
        __syncthreads();
    }
    if(t == 0) dst[0] = red[0] / 2097152.0f;
}

extern "C" void kernel_launch(void* const* d_in, const int* in_sizes, int n_in,
                              void* d_out, int out_size) {
    const float* x      = (const float*)d_in[0];
    const float* mem    = (const float*)d_in[1];
    const float* cmem   = (const float*)d_in[2];
    const float* pe     = (const float*)d_in[3];
    const float* Wq     = (const float*)d_in[4];
    const float* Wkv    = (const float*)d_in[5];
    const float* Wout   = (const float*)d_in[6];
    const float* bout   = (const float*)d_in[7];
    const float* conv_w = (const float*)d_in[8];
    const float* conv_b = (const float*)d_in[9];
    float* out = (float*)d_out;

    float* S = 0;
    cudaGetSymbolAddress((void**)&S, g_scratch);
    float* sq    = S + S_Q;
    float* skvin = S + S_KVIN;
    float* skv   = S + S_KV;
    float* scm   = S + S_CM;
    float* sckv  = S + S_CKV;
    float* sconvA= S + S_CONVA;
    float* so    = S + S_O;
    float* sauxp = S + S_AUXP;
    float* sm_   = S + S_M;
    float* sl_   = S + S_L;
    float* spe   = S + S_PE;

    const int ATTN_SMEM = (4224 + 3*4352 + 8704 + 192)*4;
    const int AUX_SMEM  = (4224 + 4*4352 + 4224 + 192 + 256)*4;
    cudaFuncSetAttribute(k_attn_mma, cudaFuncAttributeMaxDynamicSharedMemorySize, ATTN_SMEM);
    cudaFuncSetAttribute(k_aux_mma,  cudaFuncAttributeMaxDynamicSharedMemorySize, AUX_SMEM);

    static cudaStream_t s1 = 0, s2 = 0, s3 = 0;
    static cudaEvent_t eFork=0, eQ=0, eKVA=0, eKVB=0, eCKV=0, eAux=0, eAttnA=0, eAttnB=0, eRescA=0, eRescB=0;
    if(!s1){
        cudaStreamCreateWithFlags(&s1, cudaStreamNonBlocking);
        cudaStreamCreateWithFlags(&s2, cudaStreamNonBlocking);
        cudaStreamCreateWithFlags(&s3, cudaStreamNonBlocking);
        cudaEventCreateWithFlags(&eFork,  cudaEventDisableTiming);
        cudaEventCreateWithFlags(&eQ,     cudaEventDisableTiming);
        cudaEventCreateWithFlags(&eKVA,   cudaEventDisableTiming);
        cudaEventCreateWithFlags(&eKVB,   cudaEventDisableTiming);
        cudaEventCreateWithFlags(&eCKV,   cudaEventDisableTiming);
        cudaEventCreateWithFlags(&eAux,   cudaEventDisableTiming);
        cudaEventCreateWithFlags(&eAttnA, cudaEventDisableTiming);
        cudaEventCreateWithFlags(&eAttnB, cudaEventDisableTiming);
        cudaEventCreateWithFlags(&eRescA, cudaEventDisableTiming);
        cudaEventCreateWithFlags(&eRescB, cudaEventDisableTiming);
    }

    cudaEventRecord(eFork, 0);

    // ---- s1: conv chain + new_cmem ----
    cudaStreamWaitEvent(s1, eFork, 0);
    k_convA<<<(BB*CMEML*EE*4 + 255)/256, 256, 0, s1>>>(mem, sconvA);
    k_gemm_mma<1,0><<<dim3(EE/64, BB*CMEML/128), 256, 0, s1>>>(sconvA, conv_w, conv_b, scm, BB*CMEML, EE, EE*4);
    cudaMemcpyAsync(out + OFF_NEWCMEM, scm, (size_t)BB*CMEML*EE*4, cudaMemcpyDeviceToDevice, s1);
    k_gemm_mma<0,1><<<dim3(2*EE/64, BB*CMEML/128), 256, 0, s1>>>(scm, Wkv, (const float*)0, sckv, BB*CMEML, 2*EE, EE);
    cudaEventRecord(eCKV, s1);

    // ---- s3: new_mem copy + q GEMM ----
    cudaStreamWaitEvent(s3, eFork, 0);
    cudaMemcpyAsync(out + OFF_NEWMEM, x, (size_t)BB*TT*EE*4, cudaMemcpyDeviceToDevice, s3);
    k_gemm_mma<0,1><<<dim3(EE/64, BB*TT/128), 256, 0, s3>>>(x, Wq, (const float*)0, sq, BB*TT, EE, EE);
    cudaEventRecord(eQ, s3);

    // ---- s0: pe + concat + kv GEMM in two batch halves ----
    k_pe<<<(HH*PEROWS*64/4 + 255)/256, 256>>>(pe, spe);
    k_concat<<<(BB*KVL*EE/4 + 255)/256, 256>>>(x, mem, cmem, skvin);
    k_gemm_mma<0,1><<<dim3(2*EE/64, 2*KVL/128), 256>>>(skvin, Wkv, (const float*)0, skv, 2*KVL, 2*EE, EE);
    cudaEventRecord(eKVA, 0);
    k_gemm_mma<0,1><<<dim3(2*EE/64, 2*KVL/128), 256>>>(skvin + (long long)2*KVL*EE, Wkv, (const float*)0,
                                                       skv + (long long)2*KVL*2*EE, 2*KVL, 2*EE, EE);
    cudaEventRecord(eKVB, 0);

    // ---- s3: attention half A (b=0,1) ----
    cudaStreamWaitEvent(s3, eKVA, 0);
    k_attn_mma<<<dim3(TT/64, HH, 2), 256, ATTN_SMEM, s3>>>(spe, out + OFF_W, sq, skv, so, sm_, sl_, 0);
    cudaEventRecord(eAttnA, s3);

    // ---- s2: aux (needs q, full kv, ckv) — concurrent with attention ----
    cudaStreamWaitEvent(s2, eQ, 0);
    cudaStreamWaitEvent(s2, eKVB, 0);
    cudaStreamWaitEvent(s2, eCKV, 0);
    k_aux_mma<<<dim3(TT/64, HH, BB), 256, AUX_SMEM, s2>>>(sq, skv, sckv, sauxp);
    cudaEventRecord(eAux, s2);

    // ---- s0: attention half B (b=2,3) ----
    cudaStreamWaitEvent(0, eQ, 0);
    k_attn_mma<<<dim3(TT/64, HH, 2), 256, ATTN_SMEM>>>(spe, out + OFF_W, sq, skv, so, sm_, sl_, 2);
    cudaEventRecord(eAttnB, 0);

    // ---- s1: rescale half A (overlaps attn B tail); s2 handles half B after aux ----
    cudaStreamWaitEvent(s1, eAttnA, 0);
    k_rescale<<<2*HH*TT, 576, 0, s1>>>(out + OFF_W, sm_, sl_, 0);
    cudaEventRecord(eRescA, s1);
    cudaStreamWaitEvent(s2, eAttnB, 0);
    k_rescale<<<2*HH*TT, 576, 0, s2>>>(out + OFF_W, sm_, sl_, 2*HH*TT);
    cudaEventRecord(eRescB, s2);

    // ---- s0: logits (needs both attn halves) ----
    cudaStreamWaitEvent(0, eAttnA, 0);
    k_gemm_mma<0,0><<<dim3(EE/64, BB*TT/128), 256>>>(so, Wout, bout, out + OFF_LOGITS, BB*TT, EE, EE);

    // ---- join everything before the final node ----
    cudaStreamWaitEvent(0, eAux, 0);
    cudaStreamWaitEvent(0, eRescA, 0);
    cudaStreamWaitEvent(0, eRescB, 0);
    k_auxfin<<<1, 512>>>(sauxp, out + OFF_AUX);
}

// round 16
// speedup vs baseline: 1.0460x; 1.0460x over previous
#include <cuda_runtime.h>
#include <math.h>
#include <stdint.h>

#define BB 4
#define TT 1024
#define EE 512
#define HH 8
#define DHH 64
#define KVL 2304
#define MEML 1024
#define CMEML 256
#define SCL 0.125f
#define PEROWS 3456

#define OFF_LOGITS  0LL
#define OFF_NEWMEM  2097152LL
#define OFF_NEWCMEM 4194304LL
#define OFF_AUX     4718592LL
#define OFF_W       4718593LL   /* ODD -> weights region only 4B-aligned: scalar I/O only */

#define S_Q     0LL
#define S_KVIN  2097152LL
#define S_KV    6815744LL
#define S_CM    16252928LL
#define S_CKV   16777216LL
#define S_CONVA 17825792LL
#define S_O     19922944LL
#define S_AUXP  22020096LL
#define S_M     22020608LL
#define S_L     22053376LL
#define S_PE    22086144LL
#define S_TOTAL (S_PE + (long long)HH*PEROWS*64)

__device__ float g_scratch[S_TOTAL];

__device__ __forceinline__ float tf32r(float x){
    unsigned u;
    asm("cvt.rna.tf32.f32 %0, %1;" : "=r"(u) : "f"(x));
    return __uint_as_float(u);
}

__device__ __forceinline__ void mma_tf32(float d[4], const unsigned a[4], const unsigned b[2]){
    asm("mma.sync.aligned.m16n8k8.row.col.f32.tf32.tf32.f32 "
        "{%0,%1,%2,%3},{%4,%5,%6,%7},{%8,%9},{%0,%1,%2,%3};"
        : "+f"(d[0]),"+f"(d[1]),"+f"(d[2]),"+f"(d[3])
        : "r"(a[0]),"r"(a[1]),"r"(a[2]),"r"(a[3]), "r"(b[0]),"r"(b[1]));
}

__global__ void k_concat(const float* __restrict__ x, const float* __restrict__ mem,
                         const float* __restrict__ cmem, float* __restrict__ kvin){
    long long i = (long long)blockIdx.x*blockDim.x + threadIdx.x;
    const long long n4 = (long long)BB*KVL*EE/4;
    if(i >= n4) return;
    long long idx = i*4;
    int b = (int)(idx / ((long long)KVL*EE));
    int rem = (int)(idx % ((long long)KVL*EE));
    int j = rem / EE, e = rem % EE;
    const float* src;
    if(j < CMEML)            src = cmem + ((long long)b*CMEML + j)*EE + e;
    else if(j < CMEML+MEML)  src = mem  + ((long long)b*MEML + (j-CMEML))*EE + e;
    else                     src = x    + ((long long)b*TT   + (j-CMEML-MEML))*EE + e;
    ((float4*)kvin)[i] = *(const float4*)src;
}

__global__ void k_convA(const float* __restrict__ mem, float* __restrict__ convA){
    int i = blockIdx.x*blockDim.x + threadIdx.x;
    if(i >= BB*CMEML*EE*4) return;
    int b = i >> 19;
    int rem = i & ((1<<19)-1);
    int r = rem >> 11;
    int t2 = rem & 2047;
    int e = t2 >> 2, kk = t2 & 3;
    convA[i] = mem[((long long)b*MEML + r*4 + kk)*EE + e];
}

__global__ void k_pe(const float* __restrict__ pe, float* __restrict__ spe){
    int i = blockIdx.x*blockDim.x + threadIdx.x;
    if(i >= HH*PEROWS*64/4) return;
    int idx = i*4;
    int h = idx / (PEROWS*64);
    int rem = idx % (PEROWS*64);
    int r = rem >> 6, c = rem & 63;
    float4 v = make_float4(0.f,0.f,0.f,0.f);
    if(r < KVL){
        float4 s = *(const float4*)(pe + ((long long)h*KVL + r)*64 + c);
        v.x = tf32r(s.x); v.y = tf32r(s.y); v.z = tf32r(s.z); v.w = tf32r(s.w);
    }
    ((float4*)spe)[i] = v;
}

// ============ tf32 mma GEMM. RND=1 -> store tf32-rounded ============
template<int BT, int RND>
__global__ void __launch_bounds__(256) k_gemm_mma(const float* __restrict__ A,
                                                  const float* __restrict__ Bm,
                                                  const float* __restrict__ bias,
                                                  float* __restrict__ C,
                                                  int M, int N, int K){
    __shared__ float As[128*20];
    __shared__ float Bs[16*68];
    const int tid = threadIdx.x;
    const int w = tid >> 5, lane = tid & 31;
    const int g = lane >> 2, q = lane & 3;
    const int wm = w & 3, wn = w >> 2;
    const int m0 = blockIdx.y * 128;
    const int n0 = blockIdx.x * 64;

    float acc[2][4][4];
    #pragma unroll
    for(int mt=0;mt<2;mt++)
        #pragma unroll
        for(int nt=0;nt<4;nt++)
            #pragma unroll
            for(int e=0;e<4;e++) acc[mt][nt][e] = 0.f;

    const unsigned* Asu = (const unsigned*)As;
    const unsigned* Bsu = (const unsigned*)Bs;

    for(int k0=0; k0<K; k0+=16){
        #pragma unroll
        for(int li=0; li<2; li++){
            int idx = tid + li*256;
            int row = idx >> 2, c4 = (idx & 3)*4;
            float4 v = *(const float4*)(A + (long long)(m0+row)*K + k0 + c4);
            As[row*20 + c4 + 0] = tf32r(v.x);
            As[row*20 + c4 + 1] = tf32r(v.y);
            As[row*20 + c4 + 2] = tf32r(v.z);
            As[row*20 + c4 + 3] = tf32r(v.w);
        }
        if(BT){
            #pragma unroll
            for(int li=0; li<4; li++){
                int idx = tid + li*256;
                int n = idx & 63, kk = idx >> 6;
                Bs[kk*68 + n] = tf32r(Bm[(long long)(n0+n)*K + k0 + kk]);
            }
        } else {
            int row = tid >> 4, c4 = (tid & 15)*4;
            float4 v = *(const float4*)(Bm + (long long)(k0+row)*N + n0 + c4);
            Bs[row*68 + c4 + 0] = tf32r(v.x);
            Bs[row*68 + c4 + 1] = tf32r(v.y);
            Bs[row*68 + c4 + 2] = tf32r(v.z);
            Bs[row*68 + c4 + 3] = tf32r(v.w);
        }
        __syncthreads();
        #pragma unroll
        for(int k8=0; k8<2; k8++){
            int kr = k8*8;
            #pragma unroll
            for(int mt=0; mt<2; mt++){
                unsigned a[4];
                int mb = wm*32 + mt*16;
                a[0] = Asu[(mb+g)*20   + kr+q];
                a[1] = Asu[(mb+g+8)*20 + kr+q];
                a[2] = Asu[(mb+g)*20   + kr+q+4];
                a[3] = Asu[(mb+g+8)*20 + kr+q+4];
                #pragma unroll
                for(int nt=0; nt<4; nt++){
                    unsigned b[2];
                    int nb = wn*32 + nt*8;
                    b[0] = Bsu[(kr+q)*68   + nb+g];
                    b[1] = Bsu[(kr+q+4)*68 + nb+g];
                    mma_tf32(acc[mt][nt], a, b);
                }
            }
        }
        __syncthreads();
    }
    #pragma unroll
    for(int mt=0; mt<2; mt++){
        int r1 = m0 + wm*32 + mt*16 + g;
        #pragma unroll
        for(int nt=0; nt<4; nt++){
            int col = n0 + wn*32 + nt*8 + 2*q;
            float b0 = bias ? bias[col] : 0.f;
            float b1 = bias ? bias[col+1] : 0.f;
            float v0 = acc[mt][nt][0] + b0, v1 = acc[mt][nt][1] + b1;
            float v2 = acc[mt][nt][2] + b0, v3 = acc[mt][nt][3] + b1;
            if(RND){ v0=tf32r(v0); v1=tf32r(v1); v2=tf32r(v2); v3=tf32r(v3); }
            C[(long long)r1*N + col]       = v0;
            C[(long long)r1*N + col+1]     = v1;
            C[(long long)(r1+8)*N + col]   = v2;
            C[(long long)(r1+8)*N + col+1] = v3;
        }
    }
}

// ===== attention: packed Q/P, u aliased on pe, U band-skip; writes m/l =====
__global__ void __launch_bounds__(256,2) k_attn_mma(const float* __restrict__ spe,
                                                    float* __restrict__ wout,
                                                    const float* __restrict__ gq,
                                                    const float* __restrict__ gkv,
                                                    float* __restrict__ go,
                                                    float* __restrict__ gm,
                                                    float* __restrict__ gl){
    extern __shared__ float smx[];
    float* qp    = smx;                 // 4224: packed Q (A-fragments)
    float* k_s   = qp + 4224;           // 4352
    float* v_s   = k_s + 4352;          // 4352 [d][68]
    float* p_s   = v_s + 4352;          // 4352 [64][68]
    float* pu_s  = p_s + 4352;          // 8704: PE [128][68] ALIAS u [64][132] ALIAS packed P
    float* m_row = pu_s + 8704;
    float* l_row = m_row + 64;
    float* corr_row = l_row + 64;

    const int it = blockIdx.x, h = blockIdx.y, b = blockIdx.z;
    const int i0 = it*64;
    const int t = threadIdx.x;
    const int w = t >> 5, lane = t & 31;
    const int g = lane >> 2, q = lane & 3;
    const int mw = w & 3, half = w >> 2;

    // U band-skip bounds: combine reads u[i, co] only for
    // co in [48+32*half-16*mw, 94+32*half-16*mw]; a warp's nt-tile covers
    // co in [half*64+nt*8, +8). Needed iff (half==0 ? nt>=6-2*mw : nt<=7-2*mw).
    const int ntlo = half ? 0 : (6 - 2*mw);
    const int nthi = half ? (7 - 2*mw) : 7;

    const float* kbase  = gkv + ((long long)b*KVL)*1024 + h*64;
    const float* vbase  = kbase + 512;
    const float* pebase = spe + (long long)h*PEROWS*64;
    const long long wbase = (((long long)(b*HH + h))*TT + i0)*KVL;

    #pragma unroll
    for(int li=0; li<4; li++){
        int idx = t + li*256;
        int row = idx >> 4, c4 = (idx & 15)*4;
        float4 v = *(const float4*)(gq + ((long long)(b*TT+i0+row))*EE + h*64 + c4);
        int base = ((row>>4)*8 + (c4>>3))*132 + (row&7)*16 + ((row>>3)&1) + 2*((c4>>2)&1);
        qp[base+0]  = v.x;
        qp[base+4]  = v.y;
        qp[base+8]  = v.z;
        qp[base+12] = v.w;
    }
    if(t < 64){ m_row[t] = -INFINITY; l_row[t] = 0.f; }

    float oacc[4][4];
    #pragma unroll
    for(int nt=0;nt<4;nt++)
        #pragma unroll
        for(int e=0;e<4;e++) oacc[nt][e] = 0.f;

    const unsigned* ksu = (const unsigned*)k_s;
    const unsigned* vsu = (const unsigned*)v_s;
    const unsigned* peu = (const unsigned*)pu_s;

    for(int ch=0; ch<KVL/64; ch++){
        const int j0 = ch*64;
        const int rb = 960 + j0 - i0;
        const bool useU = (rb < KVL);
        __syncthreads();
        #pragma unroll
        for(int li=0; li<4; li++){
            int idx = t + li*256;
            int row = idx >> 4, c4 = (idx & 15)*4;
            *(float4*)(k_s + row*68 + c4) =
                *(const float4*)(kbase + (long long)(j0+row)*1024 + c4);
            float4 vv = *(const float4*)(vbase + (long long)(j0+row)*1024 + c4);
            v_s[(c4+0)*68 + row] = vv.x;
            v_s[(c4+1)*68 + row] = vv.y;
            v_s[(c4+2)*68 + row] = vv.z;
            v_s[(c4+3)*68 + row] = vv.w;
        }
        if(useU){
            #pragma unroll
            for(int li=0; li<8; li++){
                int idx = t + li*256;
                int row = idx >> 4, c4 = (idx & 15)*4;
                *(float4*)(pu_s + row*68 + c4) =
                    *(const float4*)(pebase + (long long)(rb+row)*64 + c4);
            }
        }
        __syncthreads();

        float uacc[8][4], sacc[4][4];
        #pragma unroll
        for(int nt=0;nt<8;nt++){ uacc[nt][0]=0.f; uacc[nt][1]=0.f; uacc[nt][2]=0.f; uacc[nt][3]=0.f; }
        #pragma unroll
        for(int nt=0;nt<4;nt++){ sacc[nt][0]=0.f; sacc[nt][1]=0.f; sacc[nt][2]=0.f; sacc[nt][3]=0.f; }
        #pragma unroll
        for(int ks=0; ks<8; ks++){
            float4 af = *(const float4*)(qp + (mw*8+ks)*132 + lane*4);
            unsigned a[4] = {__float_as_uint(af.x), __float_as_uint(af.y),
                             __float_as_uint(af.z), __float_as_uint(af.w)};
            int k0 = ks*8;
            if(useU){
                #pragma unroll
                for(int nt=0; nt<8; nt++){
                    if(nt >= ntlo && nt <= nthi){   // band skip (warp-uniform)
                        unsigned bb[2];
                        int nb = half*64 + nt*8;
                        bb[0] = peu[(nb+g)*68 + k0+q];
                        bb[1] = peu[(nb+g)*68 + k0+q+4];
                        mma_tf32(uacc[nt], a, bb);
                    }
                }
            }
            #pragma unroll
            for(int nt=0; nt<4; nt++){
                unsigned bb[2];
                int nb = half*32 + nt*8;
                bb[0] = ksu[(nb+g)*68 + k0+q];
                bb[1] = ksu[(nb+g)*68 + k0+q+4];
                mma_tf32(sacc[nt], a, bb);
            }
        }
        if(useU){
            __syncthreads();
            int i1 = mw*16 + g, i2 = i1 + 8;
            #pragma unroll
            for(int nt=0; nt<8; nt++){
                if(nt >= ntlo && nt <= nthi){
                    int rho = half*64 + nt*8 + 2*q;
                    pu_s[i1*132 + rho]   = uacc[nt][0];
                    pu_s[i1*132 + rho+1] = uacc[nt][1];
                    pu_s[i2*132 + rho]   = uacc[nt][2];
                    pu_s[i2*132 + rho+1] = uacc[nt][3];
                }
            }
            __syncthreads();
        }
        {
            int i1 = mw*16 + g, i2 = i1 + 8;
            #pragma unroll
            for(int nt=0; nt<4; nt++){
                int j_ = half*32 + nt*8 + 2*q;
                if(useU){
                    p_s[i1*68 + j_]   = SCL*(sacc[nt][0] + pu_s[i1*132 + 63 + j_   - i1]);
                    p_s[i1*68 + j_+1] = SCL*(sacc[nt][1] + pu_s[i1*132 + 63 + j_+1 - i1]);
                    p_s[i2*68 + j_]   = SCL*(sacc[nt][2] + pu_s[i2*132 + 63 + j_   - i2]);
                    p_s[i2*68 + j_+1] = SCL*(sacc[nt][3] + pu_s[i2*132 + 63 + j_+1 - i2]);
                } else {
                    p_s[i1*68 + j_]   = SCL*sacc[nt][0];
                    p_s[i1*68 + j_+1] = SCL*sacc[nt][1];
                    p_s[i2*68 + j_]   = SCL*sacc[nt][2];
                    p_s[i2*68 + j_+1] = SCL*sacc[nt][3];
                }
            }
        }
        __syncthreads();
        for(int idx=t; idx<4096; idx+=256){
            int row = idx>>6, col = idx&63;
            wout[wbase + (long long)row*KVL + j0 + col] = p_s[row*68 + col];
        }
        __syncthreads();
        {
            int r = w*8 + (lane>>2);
            int c0 = lane & 3;
            const int R8 = (r>>4)*8;
            const int WB = ((r&7)*4 + c0)*4 + ((r>>3)&1);
            float vals[16];
            float mx = -INFINITY;
            #pragma unroll
            for(int ii=0; ii<16; ii++){
                vals[ii] = p_s[r*68 + c0 + ii*4];
                mx = fmaxf(mx, vals[ii]);
            }
            mx = fmaxf(mx, __shfl_xor_sync(0xffffffffu, mx, 1));
            mx = fmaxf(mx, __shfl_xor_sync(0xffffffffu, mx, 2));
            float mo = m_row[r];
            float mn = fmaxf(mo, mx);
            float corr = __expf(mo - mn);
            float ps = 0.f;
            #pragma unroll
            for(int ii=0; ii<16; ii++){
                float p = tf32r(__expf(vals[ii] - mn));
                pu_s[(R8 + ((c0+4*ii)>>3))*132 + WB + 2*(ii&1)] = p;
                ps += p;
            }
            ps += __shfl_xor_sync(0xffffffffu, ps, 1);
            ps += __shfl_xor_sync(0xffffffffu, ps, 2);
            if((lane&3)==0){
                l_row[r] = l_row[r]*corr + ps;
                m_row[r] = mn;
                corr_row[r] = corr;
            }
        }
        __syncthreads();
        {
            float c1 = corr_row[mw*16+g], c2 = corr_row[mw*16+g+8];
            #pragma unroll
            for(int nt=0; nt<4; nt++){
                oacc[nt][0] *= c1; oacc[nt][1] *= c1;
                oacc[nt][2] *= c2; oacc[nt][3] *= c2;
            }
            #pragma unroll
            for(int ks=0; ks<8; ks++){
                float4 af = *(const float4*)(pu_s + (mw*8+ks)*132 + lane*4);
                unsigned a[4] = {__float_as_uint(af.x), __float_as_uint(af.y),
                                 __float_as_uint(af.z), __float_as_uint(af.w)};
                int k0 = ks*8;
                #pragma unroll
                for(int nt=0; nt<4; nt++){
                    unsigned bb[2];
                    int db = half*32 + nt*8;
                    bb[0] = vsu[(db+g)*68 + k0+q];
                    bb[1] = vsu[(db+g)*68 + k0+q+4];
                    mma_tf32(oacc[nt], a, bb);
                }
            }
        }
    }
    __syncthreads();
    {
        int i1 = mw*16 + g, i2 = i1 + 8;
        float inv1 = 1.f/l_row[i1], inv2 = 1.f/l_row[i2];
        #pragma unroll
        for(int nt=0; nt<4; nt++){
            int d_ = half*32 + nt*8 + 2*q;
            long long o1 = ((long long)(b*TT + i0 + i1))*EE + h*64 + d_;
            long long o2 = ((long long)(b*TT + i0 + i2))*EE + h*64 + d_;
            go[o1]   = oacc[nt][0]*inv1;
            go[o1+1] = oacc[nt][1]*inv1;
            go[o2]   = oacc[nt][2]*inv2;
            go[o2+1] = oacc[nt][3]*inv2;
        }
    }
    if(t < 64){
        long long gmi = ((long long)(b*HH + h))*TT + i0 + t;
        gm[gmi] = m_row[t];
        gl[gmi] = l_row[t];
    }
}

// separate rescale (overlaps logits GEMM + aux on other streams)
__global__ void __launch_bounds__(576) k_rescale(float* __restrict__ w,
                                                 const float* __restrict__ gm,
                                                 const float* __restrict__ gl){
    long long row = blockIdx.x;
    float mm = gm[row];
    float invl = 1.f / gl[row];
    float* wr = w + row*KVL;
    #pragma unroll
    for(int rep=0; rep<4; rep++){
        int j = threadIdx.x + rep*576;
        wr[j] = __expf(wr[j] - mm) * invl;
    }
}

// ===== aux loss: packed Q + packed P =====
__global__ void __launch_bounds__(256,2) k_aux_mma(const float* __restrict__ gq,
                                                   const float* __restrict__ gkv,
                                                   const float* __restrict__ gckv,
                                                   float* __restrict__ auxp){
    extern __shared__ float smx[];
    float* qp    = smx;                 // 4224
    float* k_s   = qp + 4224;           // 4352
    float* v_s   = k_s + 4352;          // 4352
    float* p_s   = v_s + 4352;          // 4352
    float* o1_s  = p_s + 4352;          // 4352
    float* pp    = o1_s + 4352;         // 4224 packed P
    float* m_row = pp + 4224;
    float* l_row = m_row + 64;
    float* corr_row = l_row + 64;
    float* red   = corr_row + 64;       // 256

    const int it = blockIdx.x, h = blockIdx.y, b = blockIdx.z;
    const int i0 = it*64;
    const int t = threadIdx.x;
    const int w = t >> 5, lane = t & 31;
    const int g = lane >> 2, q = lane & 3;
    const int mw = w & 3, half = w >> 2;

    #pragma unroll
    for(int li=0; li<4; li++){
        int idx = t + li*256;
        int row = idx >> 4, c4 = (idx & 15)*4;
        float4 v = *(const float4*)(gq + ((long long)(b*TT+i0+row))*EE + h*64 + c4);
        int base = ((row>>4)*8 + (c4>>3))*132 + (row&7)*16 + ((row>>3)&1) + 2*((c4>>2)&1);
        qp[base+0]  = v.x;
        qp[base+4]  = v.y;
        qp[base+8]  = v.z;
        qp[base+12] = v.w;
    }

    const unsigned* ksu = (const unsigned*)k_s;
    const unsigned* vsu = (const unsigned*)v_s;

    float dsum = 0.f;
    for(int pass=0; pass<2; pass++){
        const int nch = pass ? (CMEML/64) : (MEML/64);
        const float* kb = pass ? (gckv + ((long long)b*CMEML)*1024 + h*64)
                               : (gkv  + ((long long)(b*KVL + CMEML))*1024 + h*64);
        __syncthreads();
        if(t < 64){ m_row[t] = -INFINITY; l_row[t] = 0.f; }
        float oacc[4][4];
        #pragma unroll
        for(int nt=0;nt<4;nt++)
            #pragma unroll
            for(int e=0;e<4;e++) oacc[nt][e] = 0.f;

        for(int ch=0; ch<nch; ch++){
            const int j0 = ch*64;
            __syncthreads();
            #pragma unroll
            for(int li=0; li<4; li++){
                int idx = t + li*256;
                int row = idx >> 4, c4 = (idx & 15)*4;
                *(float4*)(k_s + row*68 + c4) =
                    *(const float4*)(kb + (long long)(j0+row)*1024 + c4);
                float4 vv = *(const float4*)(kb + (long long)(j0+row)*1024 + 512 + c4);
                v_s[(c4+0)*68 + row] = vv.x;
                v_s[(c4+1)*68 + row] = vv.y;
                v_s[(c4+2)*68 + row] = vv.z;
                v_s[(c4+3)*68 + row] = vv.w;
            }
            __syncthreads();
            float sacc[4][4];
            #pragma unroll
            for(int nt=0;nt<4;nt++){ sacc[nt][0]=0.f; sacc[nt][1]=0.f; sacc[nt][2]=0.f; sacc[nt][3]=0.f; }
            #pragma unroll
            for(int ks=0; ks<8; ks++){
                float4 af = *(const float4*)(qp + (mw*8+ks)*132 + lane*4);
                unsigned a[4] = {__float_as_uint(af.x), __float_as_uint(af.y),
                                 __float_as_uint(af.z), __float_as_uint(af.w)};
                int k0 = ks*8;
                #pragma unroll
                for(int nt=0; nt<4; nt++){
                    unsigned bb[2];
                    int nb = half*32 + nt*8;
                    bb[0] = ksu[(nb+g)*68 + k0+q];
                    bb[1] = ksu[(nb+g)*68 + k0+q+4];
                    mma_tf32(sacc[nt], a, bb);
                }
            }
            {
                int i1 = mw*16 + g, i2 = i1 + 8;
                #pragma unroll
                for(int nt=0; nt<4; nt++){
                    int j_ = half*32 + nt*8 + 2*q;
                    p_s[i1*68 + j_]   = SCL*sacc[nt][0];
                    p_s[i1*68 + j_+1] = SCL*sacc[nt][1];
                    p_s[i2*68 + j_]   = SCL*sacc[nt][2];
                    p_s[i2*68 + j_+1] = SCL*sacc[nt][3];
                }
            }
            __syncthreads();
            {
                int r = w*8 + (lane>>2);
                int c0 = lane & 3;
                const int R8 = (r>>4)*8;
                const int WB = ((r&7)*4 + c0)*4 + ((r>>3)&1);
                float vals[16];
                float mx = -INFINITY;
                #pragma unroll
                for(int ii=0; ii<16; ii++){
                    vals[ii] = p_s[r*68 + c0 + ii*4];
                    mx = fmaxf(mx, vals[ii]);
                }
                mx = fmaxf(mx, __shfl_xor_sync(0xffffffffu, mx, 1));
                mx = fmaxf(mx, __shfl_xor_sync(0xffffffffu, mx, 2));
                float mo = m_row[r];
                float mn = fmaxf(mo, mx);
                float corr = __expf(mo - mn);
                float ps = 0.f;
                #pragma unroll
                for(int ii=0; ii<16; ii++){
                    float p = tf32r(__expf(vals[ii] - mn));
                    pp[(R8 + ((c0+4*ii)>>3))*132 + WB + 2*(ii&1)] = p;
                    ps += p;
                }
                ps += __shfl_xor_sync(0xffffffffu, ps, 1);
                ps += __shfl_xor_sync(0xffffffffu, ps, 2);
                if((lane&3)==0){
                    l_row[r] = l_row[r]*corr + ps;
                    m_row[r] = mn;
                    corr_row[r] = corr;
                }
            }
            __syncthreads();
            {
                float c1 = corr_row[mw*16+g], c2 = corr_row[mw*16+g+8];
                #pragma unroll
                for(int nt=0; nt<4; nt++){
                    oacc[nt][0] *= c1; oacc[nt][1] *= c1;
                    oacc[nt][2] *= c2; oacc[nt][3] *= c2;
                }
                #pragma unroll
                for(int ks=0; ks<8; ks++){
                    float4 af = *(const float4*)(pp + (mw*8+ks)*132 + lane*4);
                    unsigned a[4] = {__float_as_uint(af.x), __float_as_uint(af.y),
                                     __float_as_uint(af.z), __float_as_uint(af.w)};
                    int k0 = ks*8;
                    #pragma unroll
                    for(int nt=0; nt<4; nt++){
                        unsigned bb[2];
                        int db = half*32 + nt*8;
                        bb[0] = vsu[(db+g)*68 + k0+q];
                        bb[1] = vsu[(db+g)*68 + k0+q+4];
                        mma_tf32(oacc[nt], a, bb);
                    }
                }
            }
        }
        __syncthreads();
        {
            int i1 = mw*16 + g, i2 = i1 + 8;
            float inv1 = 1.f/l_row[i1], inv2 = 1.f/l_row[i2];
            if(pass == 0){
                #pragma unroll
                for(int nt=0; nt<4; nt++){
                    int d_ = half*32 + nt*8 + 2*q;
                    o1_s[i1*68 + d_]   = oacc[nt][0]*inv1;
                    o1_s[i1*68 + d_+1] = oacc[nt][1]*inv1;
                    o1_s[i2*68 + d_]   = oacc[nt][2]*inv2;
                    o1_s[i2*68 + d_+1] = oacc[nt][3]*inv2;
                }
            } else {
                #pragma unroll
                for(int nt=0; nt<4; nt++){
                    int d_ = half*32 + nt*8 + 2*q;
                    float d0 = o1_s[i1*68 + d_]   - oacc[nt][0]*inv1;
                    float d1 = o1_s[i1*68 + d_+1] - oacc[nt][1]*inv1;
                    float d2 = o1_s[i2*68 + d_]   - oacc[nt][2]*inv2;
                    float d3 = o1_s[i2*68 + d_+1] - oacc[nt][3]*inv2;
                    dsum += d0*d0 + d1*d1 + d2*d2 + d3*d3;
                }
            }
        }
    }
    red[t] = dsum;
    __syncthreads();
    for(int s2=128; s2>0; s2>>=1){
        if(t < s2) red[t] += red[t + s2];
        __syncthreads();
    }
    if(t == 0)
        auxp[(blockIdx.z*8 + blockIdx.y)*16 + blockIdx.x] = red[0];
}

__global__ void k_auxfin(const float* __restrict__ auxp, float* __restrict__ dst){
    __shared__ float red[512];
    int t = threadIdx.x;
    red[t] = auxp[t];
    __syncthreads();
    for(int s2=256; s2>0; s2>>=1){
        if(t < s2) red[t] += red[t + s2];
        __syncthreads();
    }
    if(t == 0) dst[0] = red[0] / 2097152.0f;
}

extern "C" void kernel_launch(void* const* d_in, const int* in_sizes, int n_in,
                              void* d_out, int out_size) {
    const float* x      = (const float*)d_in[0];
    const float* mem    = (const float*)d_in[1];
    const float* cmem   = (const float*)d_in[2];
    const float* pe     = (const float*)d_in[3];
    const float* Wq     = (const float*)d_in[4];
    const float* Wkv    = (const float*)d_in[5];
    const float* Wout   = (const float*)d_in[6];
    const float* bout   = (const float*)d_in[7];
    const float* conv_w = (const float*)d_in[8];
    const float* conv_b = (const float*)d_in[9];
    float* out = (float*)d_out;

    float* S = 0;
    cudaGetSymbolAddress((void**)&S, g_scratch);
    float* sq    = S + S_Q;
    float* skvin = S + S_KVIN;
    float* skv   = S + S_KV;
    float* scm   = S + S_CM;
    float* sckv  = S + S_CKV;
    float* sconvA= S + S_CONVA;
    float* so    = S + S_O;
    float* sauxp = S + S_AUXP;
    float* sm_   = S + S_M;
    float* sl_   = S + S_L;
    float* spe   = S + S_PE;

    const int ATTN_SMEM = (4224 + 3*4352 + 8704 + 192)*4;
    const int AUX_SMEM  = (4224 + 4*4352 + 4224 + 192 + 256)*4;
    cudaFuncSetAttribute(k_attn_mma, cudaFuncAttributeMaxDynamicSharedMemorySize, ATTN_SMEM);
    cudaFuncSetAttribute(k_aux_mma,  cudaFuncAttributeMaxDynamicSharedMemorySize, AUX_SMEM);

    static cudaStream_t s1 = 0, s2 = 0, s3 = 0;
    static cudaEvent_t eFork = 0, eQ = 0, eKV = 0, eCKV = 0, eAux = 0, eAttn = 0, eResc = 0;
    if(!s1){
        cudaStreamCreateWithFlags(&s1, cudaStreamNonBlocking);
        cudaStreamCreateWithFlags(&s2, cudaStreamNonBlocking);
        cudaStreamCreateWithFlags(&s3, cudaStreamNonBlocking);
        cudaEventCreateWithFlags(&eFork, cudaEventDisableTiming);
        cudaEventCreateWithFlags(&eQ,    cudaEventDisableTiming);
        cudaEventCreateWithFlags(&eKV,   cudaEventDisableTiming);
        cudaEventCreateWithFlags(&eCKV,  cudaEventDisableTiming);
        cudaEventCreateWithFlags(&eAux,  cudaEventDisableTiming);
        cudaEventCreateWithFlags(&eAttn, cudaEventDisableTiming);
        cudaEventCreateWithFlags(&eResc, cudaEventDisableTiming);
    }

    // ---- fork point on the capture (default) stream ----
    cudaEventRecord(eFork, 0);

    // ---- s1: conv chain + new_cmem ----
    cudaStreamWaitEvent(s1, eFork, 0);
    k_convA<<<(BB*CMEML*EE*4 + 255)/256, 256, 0, s1>>>(mem, sconvA);
    k_gemm_mma<1,0><<<dim3(EE/64, BB*CMEML/128), 256, 0, s1>>>(sconvA, conv_w, conv_b, scm, BB*CMEML, EE, EE*4);
    cudaMemcpyAsync(out + OFF_NEWCMEM, scm, (size_t)BB*CMEML*EE*4, cudaMemcpyDeviceToDevice, s1);
    k_gemm_mma<0,1><<<dim3(2*EE/64, BB*CMEML/128), 256, 0, s1>>>(scm, Wkv, (const float*)0, sckv, BB*CMEML, 2*EE, EE);
    cudaEventRecord(eCKV, s1);

    // ---- s3: new_mem copy + q GEMM ----
    cudaStreamWaitEvent(s3, eFork, 0);
    cudaMemcpyAsync(out + OFF_NEWMEM, x, (size_t)BB*TT*EE*4, cudaMemcpyDeviceToDevice, s3);
    k_gemm_mma<0,1><<<dim3(EE/64, BB*TT/128), 256, 0, s3>>>(x, Wq, (const float*)0, sq, BB*TT, EE, EE);
    cudaEventRecord(eQ, s3);

    // ---- s0 (default): pe + kv path ----
    k_pe<<<(HH*PEROWS*64/4 + 255)/256, 256>>>(pe, spe);
    k_concat<<<(BB*KVL*EE/4 + 255)/256, 256>>>(x, mem, cmem, skvin);
    k_gemm_mma<0,1><<<dim3(2*EE/64, BB*KVL/128), 256>>>(skvin, Wkv, (const float*)0, skv, BB*KVL, 2*EE, EE);
    cudaEventRecord(eKV, 0);

    // ---- s2: aux (needs q, kv, ckv) — concurrent with attention ----
    cudaStreamWaitEvent(s2, eQ, 0);
    cudaStreamWaitEvent(s2, eKV, 0);
    cudaStreamWaitEvent(s2, eCKV, 0);
    k_aux_mma<<<dim3(TT/64, HH, BB), 256, AUX_SMEM, s2>>>(sq, skv, sckv, sauxp);
    cudaEventRecord(eAux, s2);

    // ---- s0: attention ----
    cudaStreamWaitEvent(0, eQ, 0);
    k_attn_mma<<<dim3(TT/64, HH, BB), 256, ATTN_SMEM>>>(spe, out + OFF_W, sq, skv, so, sm_, sl_);
    cudaEventRecord(eAttn, 0);

    // ---- s1: rescale (overlaps logits GEMM + aux tail) ----
    cudaStreamWaitEvent(s1, eAttn, 0);
    k_rescale<<<BB*HH*TT, 576, 0, s1>>>(out + OFF_W, sm_, sl_);
    cudaEventRecord(eResc, s1);

    // ---- s0: logits ----
    k_gemm_mma<0,0><<<dim3(EE/64, BB*TT/128), 256>>>(so, Wout, bout, out + OFF_LOGITS, BB*TT, EE, EE);

    // ---- join all side work before final node ----
    cudaStreamWaitEvent(0, eAux, 0);
    cudaStreamWaitEvent(0, eResc, 0);
    k_auxfin<<<1, 512>>>(sauxp, out + OFF_AUX);
}

// round 17
// speedup vs baseline: 1.0507x; 1.0045x over previous
#include <cuda_runtime.h>
#include <math.h>
#include <stdint.h>

#define BB 4
#define TT 1024
#define EE 512
#define HH 8
#define DHH 64
#define KVL 2304
#define MEML 1024
#define CMEML 256
#define SCL 0.125f
#define PEROWS 3456

#define OFF_LOGITS  0LL
#define OFF_NEWMEM  2097152LL
#define OFF_NEWCMEM 4194304LL
#define OFF_AUX     4718592LL
#define OFF_W       4718593LL   /* ODD -> weights region only 4B-aligned: scalar I/O only */

#define S_Q     0LL
#define S_KV    6815744LL
#define S_CM    16252928LL
#define S_CKV   16777216LL
#define S_CONVA 17825792LL
#define S_O     19922944LL
#define S_AUXP  22020096LL
#define S_M     22020608LL
#define S_L     22053376LL
#define S_PE    22086144LL
#define S_TOTAL (S_PE + (long long)HH*PEROWS*64)

__device__ float g_scratch[S_TOTAL];

__device__ __forceinline__ float tf32r(float x){
    unsigned u;
    asm("cvt.rna.tf32.f32 %0, %1;" : "=r"(u) : "f"(x));
    return __uint_as_float(u);
}

__device__ __forceinline__ void mma_tf32(float d[4], const unsigned a[4], const unsigned b[2]){
    asm("mma.sync.aligned.m16n8k8.row.col.f32.tf32.tf32.f32 "
        "{%0,%1,%2,%3},{%4,%5,%6,%7},{%8,%9},{%0,%1,%2,%3};"
        : "+f"(d[0]),"+f"(d[1]),"+f"(d[2]),"+f"(d[3])
        : "r"(a[0]),"r"(a[1]),"r"(a[2]),"r"(a[3]), "r"(b[0]),"r"(b[1]));
}

__global__ void k_convA(const float* __restrict__ mem, float* __restrict__ convA){
    int i = blockIdx.x*blockDim.x + threadIdx.x;
    if(i >= BB*CMEML*EE*4) return;
    int b = i >> 19;
    int rem = i & ((1<<19)-1);
    int r = rem >> 11;
    int t2 = rem & 2047;
    int e = t2 >> 2, kk = t2 & 3;
    convA[i] = mem[((long long)b*MEML + r*4 + kk)*EE + e];
}

__global__ void k_pe(const float* __restrict__ pe, float* __restrict__ spe){
    int i = blockIdx.x*blockDim.x + threadIdx.x;
    if(i >= HH*PEROWS*64/4) return;
    int idx = i*4;
    int h = idx / (PEROWS*64);
    int rem = idx % (PEROWS*64);
    int r = rem >> 6, c = rem & 63;
    float4 v = make_float4(0.f,0.f,0.f,0.f);
    if(r < KVL){
        float4 s = *(const float4*)(pe + ((long long)h*KVL + r)*64 + c);
        v.x = tf32r(s.x); v.y = tf32r(s.y); v.z = tf32r(s.z); v.w = tf32r(s.w);
    }
    ((float4*)spe)[i] = v;
}

// ============ tf32 mma GEMM. RND=1 -> store tf32-rounded ============
template<int BT, int RND>
__global__ void __launch_bounds__(256) k_gemm_mma(const float* __restrict__ A,
                                                  const float* __restrict__ Bm,
                                                  const float* __restrict__ bias,
                                                  float* __restrict__ C,
                                                  int M, int N, int K){
    __shared__ float As[128*20];
    __shared__ float Bs[16*68];
    const int tid = threadIdx.x;
    const int w = tid >> 5, lane = tid & 31;
    const int g = lane >> 2, q = lane & 3;
    const int wm = w & 3, wn = w >> 2;
    const int m0 = blockIdx.y * 128;
    const int n0 = blockIdx.x * 64;

    float acc[2][4][4];
    #pragma unroll
    for(int mt=0;mt<2;mt++)
        #pragma unroll
        for(int nt=0;nt<4;nt++)
            #pragma unroll
            for(int e=0;e<4;e++) acc[mt][nt][e] = 0.f;

    const unsigned* Asu = (const unsigned*)As;
    const unsigned* Bsu = (const unsigned*)Bs;

    for(int k0=0; k0<K; k0+=16){
        #pragma unroll
        for(int li=0; li<2; li++){
            int idx = tid + li*256;
            int row = idx >> 2, c4 = (idx & 3)*4;
            float4 v = *(const float4*)(A + (long long)(m0+row)*K + k0 + c4);
            As[row*20 + c4 + 0] = tf32r(v.x);
            As[row*20 + c4 + 1] = tf32r(v.y);
            As[row*20 + c4 + 2] = tf32r(v.z);
            As[row*20 + c4 + 3] = tf32r(v.w);
        }
        if(BT){
            #pragma unroll
            for(int li=0; li<4; li++){
                int idx = tid + li*256;
                int n = idx & 63, kk = idx >> 6;
                Bs[kk*68 + n] = tf32r(Bm[(long long)(n0+n)*K + k0 + kk]);
            }
        } else {
            int row = tid >> 4, c4 = (tid & 15)*4;
            float4 v = *(const float4*)(Bm + (long long)(k0+row)*N + n0 + c4);
            Bs[row*68 + c4 + 0] = tf32r(v.x);
            Bs[row*68 + c4 + 1] = tf32r(v.y);
            Bs[row*68 + c4 + 2] = tf32r(v.z);
            Bs[row*68 + c4 + 3] = tf32r(v.w);
        }
        __syncthreads();
        #pragma unroll
        for(int k8=0; k8<2; k8++){
            int kr = k8*8;
            #pragma unroll
            for(int mt=0; mt<2; mt++){
                unsigned a[4];
                int mb = wm*32 + mt*16;
                a[0] = Asu[(mb+g)*20   + kr+q];
                a[1] = Asu[(mb+g+8)*20 + kr+q];
                a[2] = Asu[(mb+g)*20   + kr+q+4];
                a[3] = Asu[(mb+g+8)*20 + kr+q+4];
                #pragma unroll
                for(int nt=0; nt<4; nt++){
                    unsigned b[2];
                    int nb = wn*32 + nt*8;
                    b[0] = Bsu[(kr+q)*68   + nb+g];
                    b[1] = Bsu[(kr+q+4)*68 + nb+g];
                    mma_tf32(acc[mt][nt], a, b);
                }
            }
        }
        __syncthreads();
    }
    #pragma unroll
    for(int mt=0; mt<2; mt++){
        int r1 = m0 + wm*32 + mt*16 + g;
        #pragma unroll
        for(int nt=0; nt<4; nt++){
            int col = n0 + wn*32 + nt*8 + 2*q;
            float b0 = bias ? bias[col] : 0.f;
            float b1 = bias ? bias[col+1] : 0.f;
            float v0 = acc[mt][nt][0] + b0, v1 = acc[mt][nt][1] + b1;
            float v2 = acc[mt][nt][2] + b0, v3 = acc[mt][nt][3] + b1;
            if(RND){ v0=tf32r(v0); v1=tf32r(v1); v2=tf32r(v2); v3=tf32r(v3); }
            C[(long long)r1*N + col]       = v0;
            C[(long long)r1*N + col+1]     = v1;
            C[(long long)(r1+8)*N + col]   = v2;
            C[(long long)(r1+8)*N + col+1] = v3;
        }
    }
}

// ============ kv GEMM with fused concat A-source (bit-identical) ============
__global__ void __launch_bounds__(256) k_gemm_kv(const float* __restrict__ x,
                                                 const float* __restrict__ mem,
                                                 const float* __restrict__ cmem,
                                                 const float* __restrict__ Bm,
                                                 float* __restrict__ C){
    const int N = 2*EE, K = EE;
    __shared__ float As[128*20];
    __shared__ float Bs[16*68];
    const int tid = threadIdx.x;
    const int w = tid >> 5, lane = tid & 31;
    const int g = lane >> 2, q = lane & 3;
    const int wm = w & 3, wn = w >> 2;
    const int m0 = blockIdx.y * 128;
    const int n0 = blockIdx.x * 64;

    // loop-invariant A-row source pointers (concat fusion)
    const float* arow[2];
    int c4v[2], rowv[2];
    #pragma unroll
    for(int li=0; li<2; li++){
        int idx = tid + li*256;
        int row = idx >> 2;
        rowv[li] = row;
        c4v[li] = (idx & 3)*4;
        int m = m0 + row;
        int b = m / KVL;
        int j = m - b*KVL;
        if(j < CMEML)            arow[li] = cmem + ((long long)b*CMEML + j)*EE;
        else if(j < CMEML+MEML)  arow[li] = mem  + ((long long)b*MEML + (j-CMEML))*EE;
        else                     arow[li] = x    + ((long long)b*TT   + (j-CMEML-MEML))*EE;
    }

    float acc[2][4][4];
    #pragma unroll
    for(int mt=0;mt<2;mt++)
        #pragma unroll
        for(int nt=0;nt<4;nt++)
            #pragma unroll
            for(int e=0;e<4;e++) acc[mt][nt][e] = 0.f;

    const unsigned* Asu = (const unsigned*)As;
    const unsigned* Bsu = (const unsigned*)Bs;

    for(int k0=0; k0<K; k0+=16){
        #pragma unroll
        for(int li=0; li<2; li++){
            float4 v = *(const float4*)(arow[li] + k0 + c4v[li]);
            int base = rowv[li]*20 + c4v[li];
            As[base + 0] = tf32r(v.x);
            As[base + 1] = tf32r(v.y);
            As[base + 2] = tf32r(v.z);
            As[base + 3] = tf32r(v.w);
        }
        {
            int row = tid >> 4, c4 = (tid & 15)*4;
            float4 v = *(const float4*)(Bm + (long long)(k0+row)*N + n0 + c4);
            Bs[row*68 + c4 + 0] = tf32r(v.x);
            Bs[row*68 + c4 + 1] = tf32r(v.y);
            Bs[row*68 + c4 + 2] = tf32r(v.z);
            Bs[row*68 + c4 + 3] = tf32r(v.w);
        }
        __syncthreads();
        #pragma unroll
        for(int k8=0; k8<2; k8++){
            int kr = k8*8;
            #pragma unroll
            for(int mt=0; mt<2; mt++){
                unsigned a[4];
                int mb = wm*32 + mt*16;
                a[0] = Asu[(mb+g)*20   + kr+q];
                a[1] = Asu[(mb+g+8)*20 + kr+q];
                a[2] = Asu[(mb+g)*20   + kr+q+4];
                a[3] = Asu[(mb+g+8)*20 + kr+q+4];
                #pragma unroll
                for(int nt=0; nt<4; nt++){
                    unsigned b[2];
                    int nb = wn*32 + nt*8;
                    b[0] = Bsu[(kr+q)*68   + nb+g];
                    b[1] = Bsu[(kr+q+4)*68 + nb+g];
                    mma_tf32(acc[mt][nt], a, b);
                }
            }
        }
        __syncthreads();
    }
    #pragma unroll
    for(int mt=0; mt<2; mt++){
        int r1 = m0 + wm*32 + mt*16 + g;
        #pragma unroll
        for(int nt=0; nt<4; nt++){
            int col = n0 + wn*32 + nt*8 + 2*q;
            C[(long long)r1*N + col]       = tf32r(acc[mt][nt][0]);
            C[(long long)r1*N + col+1]     = tf32r(acc[mt][nt][1]);
            C[(long long)(r1+8)*N + col]   = tf32r(acc[mt][nt][2]);
            C[(long long)(r1+8)*N + col+1] = tf32r(acc[mt][nt][3]);
        }
    }
}

// ===== attention: packed Q/P, u aliased on pe, U band-skip; writes m/l =====
__global__ void __launch_bounds__(256,2) k_attn_mma(const float* __restrict__ spe,
                                                    float* __restrict__ wout,
                                                    const float* __restrict__ gq,
                                                    const float* __restrict__ gkv,
                                                    float* __restrict__ go,
                                                    float* __restrict__ gm,
                                                    float* __restrict__ gl){
    extern __shared__ float smx[];
    float* qp    = smx;                 // 4224: packed Q (A-fragments)
    float* k_s   = qp + 4224;           // 4352
    float* v_s   = k_s + 4352;          // 4352 [d][68]
    float* p_s   = v_s + 4352;          // 4352 [64][68]
    float* pu_s  = p_s + 4352;          // 8704: PE [128][68] ALIAS u [64][132] ALIAS packed P
    float* m_row = pu_s + 8704;
    float* l_row = m_row + 64;
    float* corr_row = l_row + 64;

    const int it = blockIdx.x, h = blockIdx.y, b = blockIdx.z;
    const int i0 = it*64;
    const int t = threadIdx.x;
    const int w = t >> 5, lane = t & 31;
    const int g = lane >> 2, q = lane & 3;
    const int mw = w & 3, half = w >> 2;

    const int ntlo = half ? 0 : (6 - 2*mw);
    const int nthi = half ? (7 - 2*mw) : 7;

    const float* kbase  = gkv + ((long long)b*KVL)*1024 + h*64;
    const float* vbase  = kbase + 512;
    const float* pebase = spe + (long long)h*PEROWS*64;
    const long long wbase = (((long long)(b*HH + h))*TT + i0)*KVL;

    #pragma unroll
    for(int li=0; li<4; li++){
        int idx = t + li*256;
        int row = idx >> 4, c4 = (idx & 15)*4;
        float4 v = *(const float4*)(gq + ((long long)(b*TT+i0+row))*EE + h*64 + c4);
        int base = ((row>>4)*8 + (c4>>3))*132 + (row&7)*16 + ((row>>3)&1) + 2*((c4>>2)&1);
        qp[base+0]  = v.x;
        qp[base+4]  = v.y;
        qp[base+8]  = v.z;
        qp[base+12] = v.w;
    }
    if(t < 64){ m_row[t] = -INFINITY; l_row[t] = 0.f; }

    float oacc[4][4];
    #pragma unroll
    for(int nt=0;nt<4;nt++)
        #pragma unroll
        for(int e=0;e<4;e++) oacc[nt][e] = 0.f;

    const unsigned* ksu = (const unsigned*)k_s;
    const unsigned* vsu = (const unsigned*)v_s;
    const unsigned* peu = (const unsigned*)pu_s;

    for(int ch=0; ch<KVL/64; ch++){
        const int j0 = ch*64;
        const int rb = 960 + j0 - i0;
        const bool useU = (rb < KVL);
        __syncthreads();
        #pragma unroll
        for(int li=0; li<4; li++){
            int idx = t + li*256;
            int row = idx >> 4, c4 = (idx & 15)*4;
            *(float4*)(k_s + row*68 + c4) =
                *(const float4*)(kbase + (long long)(j0+row)*1024 + c4);
            float4 vv = *(const float4*)(vbase + (long long)(j0+row)*1024 + c4);
            v_s[(c4+0)*68 + row] = vv.x;
            v_s[(c4+1)*68 + row] = vv.y;
            v_s[(c4+2)*68 + row] = vv.z;
            v_s[(c4+3)*68 + row] = vv.w;
        }
        if(useU){
            #pragma unroll
            for(int li=0; li<8; li++){
                int idx = t + li*256;
                int row = idx >> 4, c4 = (idx & 15)*4;
                *(float4*)(pu_s + row*68 + c4) =
                    *(const float4*)(pebase + (long long)(rb+row)*64 + c4);
            }
        }
        __syncthreads();

        float uacc[8][4], sacc[4][4];
        #pragma unroll
        for(int nt=0;nt<8;nt++){ uacc[nt][0]=0.f; uacc[nt][1]=0.f; uacc[nt][2]=0.f; uacc[nt][3]=0.f; }
        #pragma unroll
        for(int nt=0;nt<4;nt++){ sacc[nt][0]=0.f; sacc[nt][1]=0.f; sacc[nt][2]=0.f; sacc[nt][3]=0.f; }
        #pragma unroll
        for(int ks=0; ks<8; ks++){
            float4 af = *(const float4*)(qp + (mw*8+ks)*132 + lane*4);
            unsigned a[4] = {__float_as_uint(af.x), __float_as_uint(af.y),
                             __float_as_uint(af.z), __float_as_uint(af.w)};
            int k0 = ks*8;
            if(useU){
                #pragma unroll
                for(int nt=0; nt<8; nt++){
                    if(nt >= ntlo && nt <= nthi){
                        unsigned bb[2];
                        int nb = half*64 + nt*8;
                        bb[0] = peu[(nb+g)*68 + k0+q];
                        bb[1] = peu[(nb+g)*68 + k0+q+4];
                        mma_tf32(uacc[nt], a, bb);
                    }
                }
            }
            #pragma unroll
            for(int nt=0; nt<4; nt++){
                unsigned bb[2];
                int nb = half*32 + nt*8;
                bb[0] = ksu[(nb+g)*68 + k0+q];
                bb[1] = ksu[(nb+g)*68 + k0+q+4];
                mma_tf32(sacc[nt], a, bb);
            }
        }
        if(useU){
            __syncthreads();
            int i1 = mw*16 + g, i2 = i1 + 8;
            #pragma unroll
            for(int nt=0; nt<8; nt++){
                if(nt >= ntlo && nt <= nthi){
                    int rho = half*64 + nt*8 + 2*q;
                    pu_s[i1*132 + rho]   = uacc[nt][0];
                    pu_s[i1*132 + rho+1] = uacc[nt][1];
                    pu_s[i2*132 + rho]   = uacc[nt][2];
                    pu_s[i2*132 + rho+1] = uacc[nt][3];
                }
            }
            __syncthreads();
        }
        {
            int i1 = mw*16 + g, i2 = i1 + 8;
            #pragma unroll
            for(int nt=0; nt<4; nt++){
                int j_ = half*32 + nt*8 + 2*q;
                if(useU){
                    p_s[i1*68 + j_]   = SCL*(sacc[nt][0] + pu_s[i1*132 + 63 + j_   - i1]);
                    p_s[i1*68 + j_+1] = SCL*(sacc[nt][1] + pu_s[i1*132 + 63 + j_+1 - i1]);
                    p_s[i2*68 + j_]   = SCL*(sacc[nt][2] + pu_s[i2*132 + 63 + j_   - i2]);
                    p_s[i2*68 + j_+1] = SCL*(sacc[nt][3] + pu_s[i2*132 + 63 + j_+1 - i2]);
                } else {
                    p_s[i1*68 + j_]   = SCL*sacc[nt][0];
                    p_s[i1*68 + j_+1] = SCL*sacc[nt][1];
                    p_s[i2*68 + j_]   = SCL*sacc[nt][2];
                    p_s[i2*68 + j_+1] = SCL*sacc[nt][3];
                }
            }
        }
        __syncthreads();
        // weights dump + softmax share one phase: dump reads p_s;
        // softmax reads p_s and overwrites pu_s (u-reads completed pre-sync)
        for(int idx=t; idx<4096; idx+=256){
            int row = idx>>6, col = idx&63;
            wout[wbase + (long long)row*KVL + j0 + col] = p_s[row*68 + col];
        }
        {
            int r = w*8 + (lane>>2);
            int c0 = lane & 3;
            const int R8 = (r>>4)*8;
            const int WB = ((r&7)*4 + c0)*4 + ((r>>3)&1);
            float vals[16];
            float mx = -INFINITY;
            #pragma unroll
            for(int ii=0; ii<16; ii++){
                vals[ii] = p_s[r*68 + c0 + ii*4];
                mx = fmaxf(mx, vals[ii]);
            }
            mx = fmaxf(mx, __shfl_xor_sync(0xffffffffu, mx, 1));
            mx = fmaxf(mx, __shfl_xor_sync(0xffffffffu, mx, 2));
            float mo = m_row[r];
            float mn = fmaxf(mo, mx);
            float corr = __expf(mo - mn);
            float ps = 0.f;
            #pragma unroll
            for(int ii=0; ii<16; ii++){
                float p = tf32r(__expf(vals[ii] - mn));
                pu_s[(R8 + ((c0+4*ii)>>3))*132 + WB + 2*(ii&1)] = p;
                ps += p;
            }
            ps += __shfl_xor_sync(0xffffffffu, ps, 1);
            ps += __shfl_xor_sync(0xffffffffu, ps, 2);
            if((lane&3)==0){
                l_row[r] = l_row[r]*corr + ps;
                m_row[r] = mn;
                corr_row[r] = corr;
            }
        }
        __syncthreads();
        {
            float c1 = corr_row[mw*16+g], c2 = corr_row[mw*16+g+8];
            #pragma unroll
            for(int nt=0; nt<4; nt++){
                oacc[nt][0] *= c1; oacc[nt][1] *= c1;
                oacc[nt][2] *= c2; oacc[nt][3] *= c2;
            }
            #pragma unroll
            for(int ks=0; ks<8; ks++){
                float4 af = *(const float4*)(pu_s + (mw*8+ks)*132 + lane*4);
                unsigned a[4] = {__float_as_uint(af.x), __float_as_uint(af.y),
                                 __float_as_uint(af.z), __float_as_uint(af.w)};
                int k0 = ks*8;
                #pragma unroll
                for(int nt=0; nt<4; nt++){
                    unsigned bb[2];
                    int db = half*32 + nt*8;
                    bb[0] = vsu[(db+g)*68 + k0+q];
                    bb[1] = vsu[(db+g)*68 + k0+q+4];
                    mma_tf32(oacc[nt], a, bb);
                }
            }
        }
    }
    __syncthreads();
    {
        int i1 = mw*16 + g, i2 = i1 + 8;
        float inv1 = 1.f/l_row[i1], inv2 = 1.f/l_row[i2];
        #pragma unroll
        for(int nt=0; nt<4; nt++){
            int d_ = half*32 + nt*8 + 2*q;
            long long o1 = ((long long)(b*TT + i0 + i1))*EE + h*64 + d_;
            long long o2 = ((long long)(b*TT + i0 + i2))*EE + h*64 + d_;
            go[o1]   = oacc[nt][0]*inv1;
            go[o1+1] = oacc[nt][1]*inv1;
            go[o2]   = oacc[nt][2]*inv2;
            go[o2+1] = oacc[nt][3]*inv2;
        }
    }
    if(t < 64){
        long long gmi = ((long long)(b*HH + h))*TT + i0 + t;
        gm[gmi] = m_row[t];
        gl[gmi] = l_row[t];
    }
}

// separate rescale (overlaps logits GEMM + aux on other streams)
__global__ void __launch_bounds__(576) k_rescale(float* __restrict__ w,
                                                 const float* __restrict__ gm,
                                                 const float* __restrict__ gl){
    long long row = blockIdx.x;
    float mm = gm[row];
    float invl = 1.f / gl[row];
    float* wr = w + row*KVL;
    #pragma unroll
    for(int rep=0; rep<4; rep++){
        int j = threadIdx.x + rep*576;
        wr[j] = __expf(wr[j] - mm) * invl;
    }
}

// ===== aux loss: packed Q + packed P =====
__global__ void __launch_bounds__(256,2) k_aux_mma(const float* __restrict__ gq,
                                                   const float* __restrict__ gkv,
                                                   const float* __restrict__ gckv,
                                                   float* __restrict__ auxp){
    extern __shared__ float smx[];
    float* qp    = smx;                 // 4224
    float* k_s   = qp + 4224;           // 4352
    float* v_s   = k_s + 4352;          // 4352
    float* p_s   = v_s + 4352;          // 4352
    float* o1_s  = p_s + 4352;          // 4352
    float* pp    = o1_s + 4352;         // 4224 packed P
    float* m_row = pp + 4224;
    float* l_row = m_row + 64;
    float* corr_row = l_row + 64;
    float* red   = corr_row + 64;       // 256

    const int it = blockIdx.x, h = blockIdx.y, b = blockIdx.z;
    const int i0 = it*64;
    const int t = threadIdx.x;
    const int w = t >> 5, lane = t & 31;
    const int g = lane >> 2, q = lane & 3;
    const int mw = w & 3, half = w >> 2;

    #pragma unroll
    for(int li=0; li<4; li++){
        int idx = t + li*256;
        int row = idx >> 4, c4 = (idx & 15)*4;
        float4 v = *(const float4*)(gq + ((long long)(b*TT+i0+row))*EE + h*64 + c4);
        int base = ((row>>4)*8 + (c4>>3))*132 + (row&7)*16 + ((row>>3)&1) + 2*((c4>>2)&1);
        qp[base+0]  = v.x;
        qp[base+4]  = v.y;
        qp[base+8]  = v.z;
        qp[base+12] = v.w;
    }

    const unsigned* ksu = (const unsigned*)k_s;
    const unsigned* vsu = (const unsigned*)v_s;

    float dsum = 0.f;
    for(int pass=0; pass<2; pass++){
        const int nch = pass ? (CMEML/64) : (MEML/64);
        const float* kb = pass ? (gckv + ((long long)b*CMEML)*1024 + h*64)
                               : (gkv  + ((long long)(b*KVL + CMEML))*1024 + h*64);
        __syncthreads();
        if(t < 64){ m_row[t] = -INFINITY; l_row[t] = 0.f; }
        float oacc[4][4];
        #pragma unroll
        for(int nt=0;nt<4;nt++)
            #pragma unroll
            for(int e=0;e<4;e++) oacc[nt][e] = 0.f;

        for(int ch=0; ch<nch; ch++){
            const int j0 = ch*64;
            __syncthreads();
            #pragma unroll
            for(int li=0; li<4; li++){
                int idx = t + li*256;
                int row = idx >> 4, c4 = (idx & 15)*4;
                *(float4*)(k_s + row*68 + c4) =
                    *(const float4*)(kb + (long long)(j0+row)*1024 + c4);
                float4 vv = *(const float4*)(kb + (long long)(j0+row)*1024 + 512 + c4);
                v_s[(c4+0)*68 + row] = vv.x;
                v_s[(c4+1)*68 + row] = vv.y;
                v_s[(c4+2)*68 + row] = vv.z;
                v_s[(c4+3)*68 + row] = vv.w;
            }
            __syncthreads();
            float sacc[4][4];
            #pragma unroll
            for(int nt=0;nt<4;nt++){ sacc[nt][0]=0.f; sacc[nt][1]=0.f; sacc[nt][2]=0.f; sacc[nt][3]=0.f; }
            #pragma unroll
            for(int ks=0; ks<8; ks++){
                float4 af = *(const float4*)(qp + (mw*8+ks)*132 + lane*4);
                unsigned a[4] = {__float_as_uint(af.x), __float_as_uint(af.y),
                                 __float_as_uint(af.z), __float_as_uint(af.w)};
                int k0 = ks*8;
                #pragma unroll
                for(int nt=0; nt<4; nt++){
                    unsigned bb[2];
                    int nb = half*32 + nt*8;
                    bb[0] = ksu[(nb+g)*68 + k0+q];
                    bb[1] = ksu[(nb+g)*68 + k0+q+4];
                    mma_tf32(sacc[nt], a, bb);
                }
            }
            {
                int i1 = mw*16 + g, i2 = i1 + 8;
                #pragma unroll
                for(int nt=0; nt<4; nt++){
                    int j_ = half*32 + nt*8 + 2*q;
                    p_s[i1*68 + j_]   = SCL*sacc[nt][0];
                    p_s[i1*68 + j_+1] = SCL*sacc[nt][1];
                    p_s[i2*68 + j_]   = SCL*sacc[nt][2];
                    p_s[i2*68 + j_+1] = SCL*sacc[nt][3];
                }
            }
            __syncthreads();
            {
                int r = w*8 + (lane>>2);
                int c0 = lane & 3;
                const int R8 = (r>>4)*8;
                const int WB = ((r&7)*4 + c0)*4 + ((r>>3)&1);
                float vals[16];
                float mx = -INFINITY;
                #pragma unroll
                for(int ii=0; ii<16; ii++){
                    vals[ii] = p_s[r*68 + c0 + ii*4];
                    mx = fmaxf(mx, vals[ii]);
                }
                mx = fmaxf(mx, __shfl_xor_sync(0xffffffffu, mx, 1));
                mx = fmaxf(mx, __shfl_xor_sync(0xffffffffu, mx, 2));
                float mo = m_row[r];
                float mn = fmaxf(mo, mx);
                float corr = __expf(mo - mn);
                float ps = 0.f;
                #pragma unroll
                for(int ii=0; ii<16; ii++){
                    float p = tf32r(__expf(vals[ii] - mn));
                    pp[(R8 + ((c0+4*ii)>>3))*132 + WB + 2*(ii&1)] = p;
                    ps += p;
                }
                ps += __shfl_xor_sync(0xffffffffu, ps, 1);
                ps += __shfl_xor_sync(0xffffffffu, ps, 2);
                if((lane&3)==0){
                    l_row[r] = l_row[r]*corr + ps;
                    m_row[r] = mn;
                    corr_row[r] = corr;
                }
            }
            __syncthreads();
            {
                float c1 = corr_row[mw*16+g], c2 = corr_row[mw*16+g+8];
                #pragma unroll
                for(int nt=0; nt<4; nt++){
                    oacc[nt][0] *= c1; oacc[nt][1] *= c1;
                    oacc[nt][2] *= c2; oacc[nt][3] *= c2;
                }
                #pragma unroll
                for(int ks=0; ks<8; ks++){
                    float4 af = *(const float4*)(pp + (mw*8+ks)*132 + lane*4);
                    unsigned a[4] = {__float_as_uint(af.x), __float_as_uint(af.y),
                                     __float_as_uint(af.z), __float_as_uint(af.w)};
                    int k0 = ks*8;
                    #pragma unroll
                    for(int nt=0; nt<4; nt++){
                        unsigned bb[2];
                        int db = half*32 + nt*8;
                        bb[0] = vsu[(db+g)*68 + k0+q];
                        bb[1] = vsu[(db+g)*68 + k0+q+4];
                        mma_tf32(oacc[nt], a, bb);
                    }
                }
            }
        }
        __syncthreads();
        {
            int i1 = mw*16 + g, i2 = i1 + 8;
            float inv1 = 1.f/l_row[i1], inv2 = 1.f/l_row[i2];
            if(pass == 0){
                #pragma unroll
                for(int nt=0; nt<4; nt++){
                    int d_ = half*32 + nt*8 + 2*q;
                    o1_s[i1*68 + d_]   = oacc[nt][0]*inv1;
                    o1_s[i1*68 + d_+1] = oacc[nt][1]*inv1;
                    o1_s[i2*68 + d_]   = oacc[nt][2]*inv2;
                    o1_s[i2*68 + d_+1] = oacc[nt][3]*inv2;
                }
            } else {
                #pragma unroll
                for(int nt=0; nt<4; nt++){
                    int d_ = half*32 + nt*8 + 2*q;
                    float d0 = o1_s[i1*68 + d_]   - oacc[nt][0]*inv1;
                    float d1 = o1_s[i1*68 + d_+1] - oacc[nt][1]*inv1;
                    float d2 = o1_s[i2*68 + d_]   - oacc[nt][2]*inv2;
                    float d3 = o1_s[i2*68 + d_+1] - oacc[nt][3]*inv2;
                    dsum += d0*d0 + d1*d1 + d2*d2 + d3*d3;
                }
            }
        }
    }
    red[t] = dsum;
    __syncthreads();
    for(int s2=128; s2>0; s2>>=1){
        if(t < s2) red[t] += red[t + s2];
        __syncthreads();
    }
    if(t == 0)
        auxp[(blockIdx.z*8 + blockIdx.y)*16 + blockIdx.x] = red[0];
}

__global__ void k_auxfin(const float* __restrict__ auxp, float* __restrict__ dst){
    __shared__ float red[512];
    int t = threadIdx.x;
    red[t] = auxp[t];
    __syncthreads();
    for(int s2=256; s2>0; s2>>=1){
        if(t < s2) red[t] += red[t + s2];
        __syncthreads();
    }
    if(t == 0) dst[0] = red[0] / 2097152.0f;
}

extern "C" void kernel_launch(void* const* d_in, const int* in_sizes, int n_in,
                              void* d_out, int out_size) {
    const float* x      = (const float*)d_in[0];
    const float* mem    = (const float*)d_in[1];
    const float* cmem   = (const float*)d_in[2];
    const float* pe     = (const float*)d_in[3];
    const float* Wq     = (const float*)d_in[4];
    const float* Wkv    = (const float*)d_in[5];
    const float* Wout   = (const float*)d_in[6];
    const float* bout   = (const float*)d_in[7];
    const float* conv_w = (const float*)d_in[8];
    const float* conv_b = (const float*)d_in[9];
    float* out = (float*)d_out;

    float* S = 0;
    cudaGetSymbolAddress((void**)&S, g_scratch);
    float* sq    = S + S_Q;
    float* skv   = S + S_KV;
    float* scm   = S + S_CM;
    float* sckv  = S + S_CKV;
    float* sconvA= S + S_CONVA;
    float* so    = S + S_O;
    float* sauxp = S + S_AUXP;
    float* sm_   = S + S_M;
    float* sl_   = S + S_L;
    float* spe   = S + S_PE;

    const int ATTN_SMEM = (4224 + 3*4352 + 8704 + 192)*4;
    const int AUX_SMEM  = (4224 + 4*4352 + 4224 + 192 + 256)*4;
    cudaFuncSetAttribute(k_attn_mma, cudaFuncAttributeMaxDynamicSharedMemorySize, ATTN_SMEM);
    cudaFuncSetAttribute(k_aux_mma,  cudaFuncAttributeMaxDynamicSharedMemorySize, AUX_SMEM);

    static cudaStream_t s1 = 0, s2 = 0, s3 = 0;
    static cudaEvent_t eFork = 0, eQ = 0, eKV = 0, eCKV = 0, eAux = 0, eAttn = 0, eResc = 0;
    if(!s1){
        cudaStreamCreateWithFlags(&s1, cudaStreamNonBlocking);
        cudaStreamCreateWithFlags(&s2, cudaStreamNonBlocking);
        cudaStreamCreateWithFlags(&s3, cudaStreamNonBlocking);
        cudaEventCreateWithFlags(&eFork, cudaEventDisableTiming);
        cudaEventCreateWithFlags(&eQ,    cudaEventDisableTiming);
        cudaEventCreateWithFlags(&eKV,   cudaEventDisableTiming);
        cudaEventCreateWithFlags(&eCKV,  cudaEventDisableTiming);
        cudaEventCreateWithFlags(&eAux,  cudaEventDisableTiming);
        cudaEventCreateWithFlags(&eAttn, cudaEventDisableTiming);
        cudaEventCreateWithFlags(&eResc, cudaEventDisableTiming);
    }

    // ---- fork point on the capture (default) stream ----
    cudaEventRecord(eFork, 0);

    // ---- s1: conv chain + new_cmem ----
    cudaStreamWaitEvent(s1, eFork, 0);
    k_convA<<<(BB*CMEML*EE*4 + 255)/256, 256, 0, s1>>>(mem, sconvA);
    k_gemm_mma<1,0><<<dim3(EE/64, BB*CMEML/128), 256, 0, s1>>>(sconvA, conv_w, conv_b, scm, BB*CMEML, EE, EE*4);
    cudaMemcpyAsync(out + OFF_NEWCMEM, scm, (size_t)BB*CMEML*EE*4, cudaMemcpyDeviceToDevice, s1);
    k_gemm_mma<0,1><<<dim3(2*EE/64, BB*CMEML/128), 256, 0, s1>>>(scm, Wkv, (const float*)0, sckv, BB*CMEML, 2*EE, EE);
    cudaEventRecord(eCKV, s1);

    // ---- s3: pe + new_mem copy + q GEMM ----
    cudaStreamWaitEvent(s3, eFork, 0);
    k_pe<<<(HH*PEROWS*64/4 + 255)/256, 256, 0, s3>>>(pe, spe);
    cudaMemcpyAsync(out + OFF_NEWMEM, x, (size_t)BB*TT*EE*4, cudaMemcpyDeviceToDevice, s3);
    k_gemm_mma<0,1><<<dim3(EE/64, BB*TT/128), 256, 0, s3>>>(x, Wq, (const float*)0, sq, BB*TT, EE, EE);
    cudaEventRecord(eQ, s3);

    // ---- s0 (default): kv GEMM with fused concat ----
    k_gemm_kv<<<dim3(2*EE/64, BB*KVL/128), 256>>>(x, mem, cmem, Wkv, skv);
    cudaEventRecord(eKV, 0);

    // ---- s2: aux (needs q, kv, ckv) — concurrent with attention ----
    cudaStreamWaitEvent(s2, eQ, 0);
    cudaStreamWaitEvent(s2, eKV, 0);
    cudaStreamWaitEvent(s2, eCKV, 0);
    k_aux_mma<<<dim3(TT/64, HH, BB), 256, AUX_SMEM, s2>>>(sq, skv, sckv, sauxp);
    cudaEventRecord(eAux, s2);

    // ---- s0: attention ----
    cudaStreamWaitEvent(0, eQ, 0);
    k_attn_mma<<<dim3(TT/64, HH, BB), 256, ATTN_SMEM>>>(spe, out + OFF_W, sq, skv, so, sm_, sl_);
    cudaEventRecord(eAttn, 0);

    // ---- s1: rescale (overlaps logits GEMM + aux tail) ----
    cudaStreamWaitEvent(s1, eAttn, 0);
    k_rescale<<<BB*HH*TT, 576, 0, s1>>>(out + OFF_W, sm_, sl_);
    cudaEventRecord(eResc, s1);

    // ---- s0: logits ----
    k_gemm_mma<0,0><<<dim3(EE/64, BB*TT/128), 256>>>(so, Wout, bout, out + OFF_LOGITS, BB*TT, EE, EE);

    // ---- join all side work before final node ----
    cudaStreamWaitEvent(0, eAux, 0);
    cudaStreamWaitEvent(0, eResc, 0);
    k_auxfin<<<1, 512>>>(sauxp, out + OFF_AUX);
}